// round 1
// baseline (speedup 1.0000x reference)
#include <cuda_runtime.h>

#define N_NODES 50000
#define N_EDGES 400000
#define NODE_IN 16
#define EDGE_IN 8
#define HID 16
#define TROW 272  // 17 rows (16 h-rows + 1 bias row) x 16 outputs

// Scratch (device globals: no allocation allowed)
__device__ float g_T[N_NODES * TROW];      // per-node factored tensor (54.4 MB)
__device__ float g_sum1[N_NODES * HID];
__device__ float g_sum2[N_NODES * HID];
__device__ float g_cnt[N_NODES];
__device__ float g_h1[N_NODES * HID];
__device__ int   g_is64;

// ---------------------------------------------------------------------------
// Zero accumulators + detect edge_index width (int64 vs int32).
// For int64 values < 50000 the high 32-bit words are all zero; for int32 the
// odd words are real indices (prob of 8 consecutive zeros ~ (1/50000)^8).
__global__ void k_zero(const int* __restrict__ ei_raw) {
    int i = blockIdx.x * blockDim.x + threadIdx.x;
    if (i < N_NODES * HID) { g_sum1[i] = 0.f; g_sum2[i] = 0.f; }
    if (i < N_NODES) g_cnt[i] = 0.f;
    if (i == 0) {
        int odd = 0;
        #pragma unroll
        for (int k = 0; k < 8; k++) odd |= ei_raw[2 * k + 1];
        g_is64 = (odd == 0) ? 1 : 0;
    }
}

// ---------------------------------------------------------------------------
// Per-node precompute: T[n][k][o] = sum_i x[n,i] * w2[k, i*16+o]
//                      T[n][16][o] = sum_i x[n,i] * b2[i*16+o]
// 256 threads = 16 nodes x 16 o-lanes. Grid 3125 (exact).
__global__ void k_precompute(const float* __restrict__ x,
                             const float* __restrict__ w2,
                             const float* __restrict__ b2) {
    __shared__ float w2s[HID * 256];
    __shared__ float b2s[256];
    __shared__ float xs[16][NODE_IN];
    int tid = threadIdx.x;
    for (int i = tid; i < HID * 256; i += 256) w2s[i] = w2[i];
    b2s[tid] = b2[tid];
    int nl = tid >> 4, o = tid & 15;
    int n = blockIdx.x * 16 + nl;
    xs[nl][o] = x[n * NODE_IN + o];
    __syncthreads();

    float xv[NODE_IN];
    #pragma unroll
    for (int i = 0; i < NODE_IN; i++) xv[i] = xs[nl][i];

    float* trow = &g_T[(long long)n * TROW];
    #pragma unroll
    for (int k = 0; k < HID; k++) {
        float acc = 0.f;
        #pragma unroll
        for (int i = 0; i < NODE_IN; i++) acc += xv[i] * w2s[k * 256 + i * 16 + o];
        trow[k * 16 + o] = acc;
    }
    float accb = 0.f;
    #pragma unroll
    for (int i = 0; i < NODE_IN; i++) accb += xv[i] * b2s[i * 16 + o];
    trow[256 + o] = accb;
}

// ---------------------------------------------------------------------------
// Edge pass: h = relu(ea @ w1 + b1); msg[o] = T[src][16][o] + sum_k h[k]*T[src][k][o]
// atomicAdd into sum buffer (+ degree count on layer 1).
// 256 threads = 16 edges x 16 o-lanes. Grid 25000 (exact).
__global__ void k_edge(const float* __restrict__ ea,
                       const void* __restrict__ eidx,
                       const float* __restrict__ w1,
                       const float* __restrict__ b1,
                       int layer) {
    __shared__ float w1s[EDGE_IN * HID];
    __shared__ float b1s[HID];
    int tid = threadIdx.x;
    if (tid < EDGE_IN * HID) w1s[tid] = w1[tid];
    if (tid < HID) b1s[tid] = b1[tid];
    __syncthreads();

    int lane = tid & 31;
    int o = tid & 15;
    int gb = lane & 16;                 // base lane of this 16-group within warp
    int e = blockIdx.x * 16 + (tid >> 4);

    int src, dst;
    if (g_is64) {
        const long long* ei = (const long long*)eidx;
        src = (int)ei[e];
        dst = (int)ei[N_EDGES + e];
    } else {
        const int* ei = (const int*)eidx;
        src = ei[e];
        dst = ei[N_EDGES + e];
    }

    // edge MLP: lane o holds ea[o] (o<8); broadcast within group via shuffle
    float eav = (o < EDGE_IN) ? ea[(long long)e * EDGE_IN + o] : 0.f;
    float h = b1s[o];
    #pragma unroll
    for (int i = 0; i < EDGE_IN; i++) {
        float eai = __shfl_sync(0xffffffffu, eav, gb + i);
        h += eai * w1s[i * HID + o];
    }
    h = fmaxf(h, 0.f);

    // contraction with the per-source-node factored tensor
    const float* trow = &g_T[(long long)src * TROW];
    float acc = trow[256 + o];          // bias row
    #pragma unroll
    for (int k = 0; k < HID; k++) {
        float hk = __shfl_sync(0xffffffffu, h, gb + k);
        acc += hk * trow[k * 16 + o];
    }

    float* sum_out = (layer == 1) ? g_sum1 : g_sum2;
    atomicAdd(&sum_out[(long long)dst * HID + o], acc);
    if (layer == 1 && o == 0) atomicAdd(&g_cnt[dst], 1.f);
}

// ---------------------------------------------------------------------------
// Layer-1 update (scatter-mean + root + bias + relu) fused with layer-2
// precompute of T from h1. 256 threads = 16 nodes x 16 o-lanes. Grid 3125.
__global__ void k_update1_pre2(const float* __restrict__ x,
                               const float* __restrict__ root1,
                               const float* __restrict__ bias1,
                               const float* __restrict__ w2,
                               const float* __restrict__ b2) {
    __shared__ float w2s[HID * 256];
    __shared__ float b2s[256];
    __shared__ float roots[NODE_IN * HID];
    __shared__ float biass[HID];
    __shared__ float xs[16][NODE_IN];
    __shared__ float hs[16][HID];
    int tid = threadIdx.x;
    for (int i = tid; i < HID * 256; i += 256) w2s[i] = w2[i];
    b2s[tid] = b2[tid];
    roots[tid] = root1[tid];
    if (tid < HID) biass[tid] = bias1[tid];
    int nl = tid >> 4, o = tid & 15;
    int n = blockIdx.x * 16 + nl;
    xs[nl][o] = x[n * NODE_IN + o];
    __syncthreads();

    float inv = 1.f / fmaxf(g_cnt[n], 1.f);
    float h = g_sum1[(long long)n * HID + o] * inv + biass[o];
    #pragma unroll
    for (int i = 0; i < NODE_IN; i++) h += xs[nl][i] * roots[i * HID + o];
    h = fmaxf(h, 0.f);
    g_h1[(long long)n * HID + o] = h;
    hs[nl][o] = h;
    __syncthreads();

    float xv[HID];
    #pragma unroll
    for (int i = 0; i < HID; i++) xv[i] = hs[nl][i];

    float* trow = &g_T[(long long)n * TROW];
    #pragma unroll
    for (int k = 0; k < HID; k++) {
        float acc = 0.f;
        #pragma unroll
        for (int i = 0; i < HID; i++) acc += xv[i] * w2s[k * 256 + i * 16 + o];
        trow[k * 16 + o] = acc;
    }
    float accb = 0.f;
    #pragma unroll
    for (int i = 0; i < HID; i++) accb += xv[i] * b2s[i * 16 + o];
    trow[256 + o] = accb;
}

// ---------------------------------------------------------------------------
// Layer-2 update + q head. One thread per node.
__global__ void k_final(const float* __restrict__ root2,
                        const float* __restrict__ bias2,
                        const float* __restrict__ qw,
                        const float* __restrict__ qb,
                        float* __restrict__ out) {
    __shared__ float roots[HID * HID];
    __shared__ float biass[HID];
    __shared__ float qws[HID];
    int tid = threadIdx.x;
    roots[tid] = root2[tid];
    if (tid < HID) { biass[tid] = bias2[tid]; qws[tid] = qw[tid]; }
    __syncthreads();

    int n = blockIdx.x * 256 + tid;
    if (n >= N_NODES) return;
    float inv = 1.f / fmaxf(g_cnt[n], 1.f);
    float h1v[HID];
    #pragma unroll
    for (int i = 0; i < HID; i++) h1v[i] = g_h1[(long long)n * HID + i];
    float res = qb[0];
    #pragma unroll
    for (int o = 0; o < HID; o++) {
        float h2 = g_sum2[(long long)n * HID + o] * inv + biass[o];
        #pragma unroll
        for (int i = 0; i < HID; i++) h2 += h1v[i] * roots[i * HID + o];
        h2 = fmaxf(h2, 0.f);
        res += h2 * qws[o];
    }
    out[n] = res;
}

// ---------------------------------------------------------------------------
extern "C" void kernel_launch(void* const* d_in, const int* in_sizes, int n_in,
                              void* d_out, int out_size) {
    const float* x        = (const float*)d_in[0];
    const float* edge_attr= (const float*)d_in[1];
    const float* e1_w1    = (const float*)d_in[2];
    const float* e1_b1    = (const float*)d_in[3];
    const float* e1_w2    = (const float*)d_in[4];
    const float* e1_b2    = (const float*)d_in[5];
    const float* root1    = (const float*)d_in[6];
    const float* bias1    = (const float*)d_in[7];
    const float* e2_w1    = (const float*)d_in[8];
    const float* e2_b1    = (const float*)d_in[9];
    const float* e2_w2    = (const float*)d_in[10];
    const float* e2_b2    = (const float*)d_in[11];
    const float* root2    = (const float*)d_in[12];
    const float* bias2    = (const float*)d_in[13];
    const float* q_w      = (const float*)d_in[14];
    const float* q_b      = (const float*)d_in[15];
    const void*  eidx     = d_in[16];
    float* out = (float*)d_out;

    k_zero<<<(N_NODES * HID + 255) / 256, 256>>>((const int*)eidx);
    k_precompute<<<N_NODES / 16, 256>>>(x, e1_w2, e1_b2);
    k_edge<<<N_EDGES / 16, 256>>>(edge_attr, eidx, e1_w1, e1_b1, 1);
    k_update1_pre2<<<N_NODES / 16, 256>>>(x, root1, bias1, e2_w2, e2_b2);
    k_edge<<<N_EDGES / 16, 256>>>(edge_attr, eidx, e2_w1, e2_b1, 2);
    k_final<<<(N_NODES + 255) / 256, 256>>>(root2, bias2, q_w, q_b, out);
}

// round 3
// speedup vs baseline: 1.0838x; 1.0838x over previous
#include <cuda_runtime.h>

#define N_NODES 50000
#define N_EDGES 400000
#define NODE_IN 16
#define EDGE_IN 8
#define HID 16
#define TROW 272  // 17 rows (16 h-rows + 1 bias row) x 16 outputs
#define NPB 64    // nodes per block in node kernels
#define NPT 4     // nodes per thread
#define NODE_GRID ((N_NODES + NPB - 1) / NPB)  // 782

// Scratch (device globals: no allocation allowed)
__device__ float g_T[N_NODES * TROW];      // per-node factored tensor (54.4 MB)
__device__ float g_sum1[N_NODES * HID];
__device__ float g_sum2[N_NODES * HID];
__device__ float g_cnt[N_NODES];
__device__ float g_h1[N_NODES * HID];
__device__ int   g_is64;

// ---------------------------------------------------------------------------
// Layer-1 per-node precompute: T[n][k][o] = sum_i x[n,i] * w2[k, i*16+o]
//                              T[n][16][o] = sum_i x[n,i] * b2[i*16+o]
// Fused: accumulator zeroing + edge_index width detection.
// 256 threads = 16 groups x 16 o-lanes; each group owns 4 nodes -> each w2
// LDS feeds 4 FFMAs (4x fewer shared loads than 1-node-per-thread).
__global__ void __launch_bounds__(256) k_precompute(const float* __restrict__ x,
                                                    const float* __restrict__ w2,
                                                    const float* __restrict__ b2,
                                                    const int* __restrict__ ei_raw) {
    __shared__ float w2s[HID * 256];
    __shared__ float b2s[256];
    __shared__ float xs[NPB * NODE_IN];
    int tid = threadIdx.x;
    int gid = blockIdx.x * 256 + tid;

    // fused zeroing of accumulators (kernel boundary orders vs. edge pass)
    const int TOT = NODE_GRID * 256;
    for (int j = gid; j < N_NODES * HID; j += TOT) { g_sum1[j] = 0.f; g_sum2[j] = 0.f; }
    if (gid < N_NODES) g_cnt[gid] = 0.f;
    if (gid == 0) {
        int odd = 0;
        #pragma unroll
        for (int k = 0; k < 8; k++) odd |= ei_raw[2 * k + 1];
        g_is64 = (odd == 0) ? 1 : 0;
    }

    for (int i = tid; i < HID * 256; i += 256) w2s[i] = w2[i];
    b2s[tid] = b2[tid];
    int nb = blockIdx.x * NPB;
    for (int idx = tid; idx < NPB * NODE_IN; idx += 256) {
        int n = nb + (idx >> 4);
        xs[idx] = (n < N_NODES) ? x[n * NODE_IN + (idx & 15)] : 0.f;
    }
    __syncthreads();

    int o = tid & 15;
    int nl0 = (tid >> 4) * NPT;

    float xv[NPT][NODE_IN];
    #pragma unroll
    for (int j = 0; j < NPT; j++)
        #pragma unroll
        for (int i = 0; i < NODE_IN; i++)
            xv[j][i] = xs[(nl0 + j) * NODE_IN + i];

    #pragma unroll 1
    for (int k = 0; k < HID; k++) {
        float acc[NPT] = {0.f, 0.f, 0.f, 0.f};
        #pragma unroll
        for (int i = 0; i < NODE_IN; i++) {
            float w = w2s[k * 256 + i * 16 + o];
            #pragma unroll
            for (int j = 0; j < NPT; j++) acc[j] += xv[j][i] * w;
        }
        #pragma unroll
        for (int j = 0; j < NPT; j++) {
            int n = nb + nl0 + j;
            if (n < N_NODES) g_T[(long long)n * TROW + k * 16 + o] = acc[j];
        }
    }
    {
        float acc[NPT] = {0.f, 0.f, 0.f, 0.f};
        #pragma unroll
        for (int i = 0; i < NODE_IN; i++) {
            float w = b2s[i * 16 + o];
            #pragma unroll
            for (int j = 0; j < NPT; j++) acc[j] += xv[j][i] * w;
        }
        #pragma unroll
        for (int j = 0; j < NPT; j++) {
            int n = nb + nl0 + j;
            if (n < N_NODES) g_T[(long long)n * TROW + 256 + o] = acc[j];
        }
    }
}

// ---------------------------------------------------------------------------
// Edge pass: h = relu(ea @ w1 + b1); msg[o] = T[src][16][o] + sum_k h[k]*T[src][k][o]
// atomicAdd into sum buffer (+ degree count on layer 1).
// 256 threads = 16 edges x 16 o-lanes. Grid 25000 (exact).
__global__ void __launch_bounds__(256) k_edge(const float* __restrict__ ea,
                                              const void* __restrict__ eidx,
                                              const float* __restrict__ w1,
                                              const float* __restrict__ b1,
                                              int layer) {
    __shared__ float w1s[EDGE_IN * HID];
    __shared__ float b1s[HID];
    int tid = threadIdx.x;
    if (tid < EDGE_IN * HID) w1s[tid] = w1[tid];
    if (tid < HID) b1s[tid] = b1[tid];
    __syncthreads();

    int lane = tid & 31;
    int o = tid & 15;
    int gb = lane & 16;                 // base lane of this 16-group within warp
    int e = blockIdx.x * 16 + (tid >> 4);

    int src, dst;
    if (g_is64) {
        const long long* ei = (const long long*)eidx;
        src = (int)ei[e];
        dst = (int)ei[N_EDGES + e];
    } else {
        const int* ei = (const int*)eidx;
        src = ei[e];
        dst = ei[N_EDGES + e];
    }

    // edge MLP: lane o holds ea[o] (o<8); broadcast within group via shuffle
    float eav = (o < EDGE_IN) ? ea[(long long)e * EDGE_IN + o] : 0.f;
    float h = b1s[o];
    #pragma unroll
    for (int i = 0; i < EDGE_IN; i++) {
        float eai = __shfl_sync(0xffffffffu, eav, gb + i);
        h += eai * w1s[i * HID + o];
    }
    h = fmaxf(h, 0.f);

    // contraction with the per-source-node factored tensor
    const float* trow = &g_T[(long long)src * TROW];
    float acc = trow[256 + o];          // bias row
    #pragma unroll
    for (int k = 0; k < HID; k++) {
        float hk = __shfl_sync(0xffffffffu, h, gb + k);
        acc += hk * trow[k * 16 + o];
    }

    float* sum_out = (layer == 1) ? g_sum1 : g_sum2;
    atomicAdd(&sum_out[(long long)dst * HID + o], acc);
    if (layer == 1 && o == 0) atomicAdd(&g_cnt[dst], 1.f);
}

// ---------------------------------------------------------------------------
// Layer-1 update (scatter-mean + root + bias + relu) fused with layer-2
// precompute of T from h1. Same 4-nodes-per-thread amortization.
__global__ void __launch_bounds__(256) k_update1_pre2(const float* __restrict__ x,
                                                      const float* __restrict__ root1,
                                                      const float* __restrict__ bias1,
                                                      const float* __restrict__ w2,
                                                      const float* __restrict__ b2) {
    __shared__ float w2s[HID * 256];
    __shared__ float b2s[256];
    __shared__ float roots[NODE_IN * HID];
    __shared__ float biass[HID];
    __shared__ float xs[NPB * NODE_IN];
    __shared__ float hs[NPB * HID];
    int tid = threadIdx.x;
    for (int i = tid; i < HID * 256; i += 256) w2s[i] = w2[i];
    b2s[tid] = b2[tid];
    roots[tid] = root1[tid];
    if (tid < HID) biass[tid] = bias1[tid];
    int nb = blockIdx.x * NPB;
    for (int idx = tid; idx < NPB * NODE_IN; idx += 256) {
        int n = nb + (idx >> 4);
        xs[idx] = (n < N_NODES) ? x[n * NODE_IN + (idx & 15)] : 0.f;
    }
    __syncthreads();

    int o = tid & 15;
    int nl0 = (tid >> 4) * NPT;

    // layer-1 node update for this thread's 4 nodes (fixed o)
    #pragma unroll
    for (int j = 0; j < NPT; j++) {
        int n = nb + nl0 + j;
        float h = 0.f;
        if (n < N_NODES) {
            float inv = 1.f / fmaxf(g_cnt[n], 1.f);
            h = g_sum1[(long long)n * HID + o] * inv + biass[o];
            #pragma unroll
            for (int i = 0; i < NODE_IN; i++)
                h += xs[(nl0 + j) * NODE_IN + i] * roots[i * HID + o];
            h = fmaxf(h, 0.f);
            g_h1[(long long)n * HID + o] = h;
        }
        hs[(nl0 + j) * HID + o] = h;
    }
    __syncthreads();

    float hv[NPT][HID];
    #pragma unroll
    for (int j = 0; j < NPT; j++)
        #pragma unroll
        for (int i = 0; i < HID; i++)
            hv[j][i] = hs[(nl0 + j) * HID + i];

    #pragma unroll 1
    for (int k = 0; k < HID; k++) {
        float acc[NPT] = {0.f, 0.f, 0.f, 0.f};
        #pragma unroll
        for (int i = 0; i < HID; i++) {
            float w = w2s[k * 256 + i * 16 + o];
            #pragma unroll
            for (int j = 0; j < NPT; j++) acc[j] += hv[j][i] * w;
        }
        #pragma unroll
        for (int j = 0; j < NPT; j++) {
            int n = nb + nl0 + j;
            if (n < N_NODES) g_T[(long long)n * TROW + k * 16 + o] = acc[j];
        }
    }
    {
        float acc[NPT] = {0.f, 0.f, 0.f, 0.f};
        #pragma unroll
        for (int i = 0; i < HID; i++) {
            float w = b2s[i * 16 + o];
            #pragma unroll
            for (int j = 0; j < NPT; j++) acc[j] += hv[j][i] * w;
        }
        #pragma unroll
        for (int j = 0; j < NPT; j++) {
            int n = nb + nl0 + j;
            if (n < N_NODES) g_T[(long long)n * TROW + 256 + o] = acc[j];
        }
    }
}

// ---------------------------------------------------------------------------
// Layer-2 update + q head. One thread per node.
__global__ void __launch_bounds__(256) k_final(const float* __restrict__ root2,
                                               const float* __restrict__ bias2,
                                               const float* __restrict__ qw,
                                               const float* __restrict__ qb,
                                               float* __restrict__ out) {
    __shared__ float roots[HID * HID];
    __shared__ float biass[HID];
    __shared__ float qws[HID];
    int tid = threadIdx.x;
    roots[tid] = root2[tid];
    if (tid < HID) { biass[tid] = bias2[tid]; qws[tid] = qw[tid]; }
    __syncthreads();

    int n = blockIdx.x * 256 + tid;
    if (n >= N_NODES) return;
    float inv = 1.f / fmaxf(g_cnt[n], 1.f);
    float h1v[HID];
    const float4* h1p = (const float4*)&g_h1[(long long)n * HID];
    #pragma unroll
    for (int i = 0; i < HID / 4; i++) {
        float4 v = h1p[i];
        h1v[i * 4 + 0] = v.x; h1v[i * 4 + 1] = v.y;
        h1v[i * 4 + 2] = v.z; h1v[i * 4 + 3] = v.w;
    }
    float res = qb[0];
    #pragma unroll
    for (int o = 0; o < HID; o++) {
        float h2 = g_sum2[(long long)n * HID + o] * inv + biass[o];
        #pragma unroll
        for (int i = 0; i < HID; i++) h2 += h1v[i] * roots[i * HID + o];
        h2 = fmaxf(h2, 0.f);
        res += h2 * qws[o];
    }
    out[n] = res;
}

// ---------------------------------------------------------------------------
extern "C" void kernel_launch(void* const* d_in, const int* in_sizes, int n_in,
                              void* d_out, int out_size) {
    const float* x        = (const float*)d_in[0];
    const float* edge_attr= (const float*)d_in[1];
    const float* e1_w1    = (const float*)d_in[2];
    const float* e1_b1    = (const float*)d_in[3];
    const float* e1_w2    = (const float*)d_in[4];
    const float* e1_b2    = (const float*)d_in[5];
    const float* root1    = (const float*)d_in[6];
    const float* bias1    = (const float*)d_in[7];
    const float* e2_w1    = (const float*)d_in[8];
    const float* e2_b1    = (const float*)d_in[9];
    const float* e2_w2    = (const float*)d_in[10];
    const float* e2_b2    = (const float*)d_in[11];
    const float* root2    = (const float*)d_in[12];
    const float* bias2    = (const float*)d_in[13];
    const float* q_w      = (const float*)d_in[14];
    const float* q_b      = (const float*)d_in[15];
    const void*  eidx     = d_in[16];
    float* out = (float*)d_out;

    k_precompute<<<NODE_GRID, 256>>>(x, e1_w2, e1_b2, (const int*)eidx);
    k_edge<<<N_EDGES / 16, 256>>>(edge_attr, eidx, e1_w1, e1_b1, 1);
    k_update1_pre2<<<NODE_GRID, 256>>>(x, root1, bias1, e2_w2, e2_b2);
    k_edge<<<N_EDGES / 16, 256>>>(edge_attr, eidx, e2_w1, e2_b1, 2);
    k_final<<<(N_NODES + 255) / 256, 256>>>(root2, bias2, q_w, q_b, out);
}

// round 7
// speedup vs baseline: 1.3436x; 1.2398x over previous
#include <cuda_runtime.h>

#define N_NODES 50000
#define N_EDGES 400000
#define NODE_IN 16
#define EDGE_IN 8
#define HID 16
#define TROWP 288  // padded: 17 rows x 16 + 16 pad -> 1152B = 9 full cache lines
#define NPB 64     // nodes per block in node kernels
#define NPT 4      // nodes per thread
#define NODE_GRID ((N_NODES + NPB - 1) / NPB)  // 782

// Scratch (device globals: no allocation allowed)
__device__ float g_T[N_NODES * TROWP];     // per-node factored tensor (57.6 MB)
__device__ float g_sum1[N_NODES * HID];
__device__ float g_sum2[N_NODES * HID];
__device__ float g_cnt[N_NODES];
__device__ float g_h1[N_NODES * HID];
__device__ int   g_is64;

// ---------------------------------------------------------------------------
// Layer-1 per-node precompute: T[n][k][o] = sum_i x[n,i] * w2[k, i*16+o]
//                              T[n][16][o] = sum_i x[n,i] * b2[i*16+o]
// Fused: accumulator zeroing + edge_index width detection.
__global__ void __launch_bounds__(256) k_precompute(const float* __restrict__ x,
                                                    const float* __restrict__ w2,
                                                    const float* __restrict__ b2,
                                                    const int* __restrict__ ei_raw) {
    __shared__ float w2s[HID * 256];
    __shared__ float b2s[256];
    __shared__ float xs[NPB * NODE_IN];
    int tid = threadIdx.x;
    int gid = blockIdx.x * 256 + tid;

    const int TOT = NODE_GRID * 256;
    for (int j = gid; j < N_NODES * HID; j += TOT) { g_sum1[j] = 0.f; g_sum2[j] = 0.f; }
    if (gid < N_NODES) g_cnt[gid] = 0.f;
    if (gid == 0) {
        int odd = 0;
        #pragma unroll
        for (int k = 0; k < 8; k++) odd |= ei_raw[2 * k + 1];
        g_is64 = (odd == 0) ? 1 : 0;
    }

    for (int i = tid; i < HID * 256; i += 256) w2s[i] = w2[i];
    b2s[tid] = b2[tid];
    int nb = blockIdx.x * NPB;
    for (int idx = tid; idx < NPB * NODE_IN; idx += 256) {
        int n = nb + (idx >> 4);
        xs[idx] = (n < N_NODES) ? x[n * NODE_IN + (idx & 15)] : 0.f;
    }
    __syncthreads();

    int o = tid & 15;
    int nl0 = (tid >> 4) * NPT;

    float xv[NPT][NODE_IN];
    #pragma unroll
    for (int j = 0; j < NPT; j++)
        #pragma unroll
        for (int i = 0; i < NODE_IN; i++)
            xv[j][i] = xs[(nl0 + j) * NODE_IN + i];

    #pragma unroll 1
    for (int k = 0; k < HID; k++) {
        float acc[NPT] = {0.f, 0.f, 0.f, 0.f};
        #pragma unroll
        for (int i = 0; i < NODE_IN; i++) {
            float w = w2s[k * 256 + i * 16 + o];
            #pragma unroll
            for (int j = 0; j < NPT; j++) acc[j] += xv[j][i] * w;
        }
        #pragma unroll
        for (int j = 0; j < NPT; j++) {
            int n = nb + nl0 + j;
            if (n < N_NODES) g_T[(long long)n * TROWP + k * 16 + o] = acc[j];
        }
    }
    {
        float acc[NPT] = {0.f, 0.f, 0.f, 0.f};
        #pragma unroll
        for (int i = 0; i < NODE_IN; i++) {
            float w = b2s[i * 16 + o];
            #pragma unroll
            for (int j = 0; j < NPT; j++) acc[j] += xv[j][i] * w;
        }
        #pragma unroll
        for (int j = 0; j < NPT; j++) {
            int n = nb + nl0 + j;
            if (n < N_NODES) g_T[(long long)n * TROWP + 256 + o] = acc[j];
        }
    }
}

// ---------------------------------------------------------------------------
// Edge pass, 8 lanes per edge, float4 loads, vector red scatter.
// lane l in [0,8): c = l&3 (output quad), half = l>>2 (even/odd k rows).
// T loads: 9 x LDG.128; load r covers rows {2r, 2r+1}: lane half=0 gets row 2r
// (outputs 4c..4c+3), half=1 gets row 2r+1. r=8 gives bias row (half=0) / pad.
// 256 threads = 32 edges/block. Grid 12500 (exact).
__global__ void __launch_bounds__(256) k_edge(const float* __restrict__ ea,
                                              const void* __restrict__ eidx,
                                              const float* __restrict__ w1,
                                              const float* __restrict__ b1,
                                              int layer) {
    __shared__ float w1s[EDGE_IN * HID];
    __shared__ float b1s[HID];
    int tid = threadIdx.x;
    if (tid < EDGE_IN * HID) w1s[tid] = w1[tid];
    if (tid < HID) b1s[tid] = b1[tid];
    __syncthreads();

    int lane = tid & 31;
    int l = lane & 7;
    int half = l >> 2;
    int c = l & 3;
    int base = lane & ~7;                // 8-lane group base within warp
    int e = blockIdx.x * 32 + (tid >> 5) * 4 + ((lane >> 3) & 3);

    int src, dst;
    if (g_is64) {
        const long long* ei = (const long long*)eidx;
        src = (int)ei[e];
        dst = (int)ei[N_EDGES + e];
    } else {
        const int* ei = (const int*)eidx;
        src = ei[e];
        dst = ei[N_EDGES + e];
    }

    // edge MLP: every lane loads all 8 ea values (32B, broadcast within group)
    const float4* eap = (const float4*)(ea + (long long)e * EDGE_IN);
    float4 a0 = eap[0], a1 = eap[1];
    float eav[EDGE_IN] = {a0.x, a0.y, a0.z, a0.w, a1.x, a1.y, a1.z, a1.w};
    // lane l computes h[l] and h[l+8]
    float hA = b1s[l], hB = b1s[l + 8];
    #pragma unroll
    for (int i = 0; i < EDGE_IN; i++) {
        hA += eav[i] * w1s[i * HID + l];
        hB += eav[i] * w1s[i * HID + l + 8];
    }
    hA = fmaxf(hA, 0.f);
    hB = fmaxf(hB, 0.f);

    // gather factored tensor: 9 x LDG.128, exactly one 128B line per (r, edge)
    const float4* tp = (const float4*)(g_T + (long long)src * TROWP);
    float4 t[9];
    #pragma unroll
    for (int r = 0; r < 9; r++) t[r] = tp[r * 8 + l];

    // contraction over this lane's 8 k-rows (k = 2r + half)
    float4 m;
    if (half == 0) m = t[8];             // bias row
    else { m.x = 0.f; m.y = 0.f; m.z = 0.f; m.w = 0.f; }
    #pragma unroll
    for (int r = 0; r < 8; r++) {
        // k = 2r + half; h[k] lives on lane (k&7) as hA (k<8) / hB (k>=8)
        float hk;
        if (r < 4) hk = __shfl_sync(0xffffffffu, hA, base + ((2 * r + half) & 7));
        else       hk = __shfl_sync(0xffffffffu, hB, base + ((2 * r + half) & 7));
        m.x += hk * t[r].x;
        m.y += hk * t[r].y;
        m.z += hk * t[r].z;
        m.w += hk * t[r].w;
    }

    // fold odd-k half into even-k half
    m.x += __shfl_xor_sync(0xffffffffu, m.x, 4);
    m.y += __shfl_xor_sync(0xffffffffu, m.y, 4);
    m.z += __shfl_xor_sync(0xffffffffu, m.z, 4);
    m.w += __shfl_xor_sync(0xffffffffu, m.w, 4);

    if (half == 0) {
        float* sum_out = (layer == 1) ? g_sum1 : g_sum2;
        float* p = sum_out + (long long)dst * HID + c * 4;
        asm volatile("red.global.add.v4.f32 [%0], {%1, %2, %3, %4};"
                     :: "l"(p), "f"(m.x), "f"(m.y), "f"(m.z), "f"(m.w)
                     : "memory");
    }
    if (layer == 1 && l == 0) atomicAdd(&g_cnt[dst], 1.f);
}

// ---------------------------------------------------------------------------
// Layer-1 update (scatter-mean + root + bias + relu) fused with layer-2
// precompute of T from h1.
__global__ void __launch_bounds__(256) k_update1_pre2(const float* __restrict__ x,
                                                      const float* __restrict__ root1,
                                                      const float* __restrict__ bias1,
                                                      const float* __restrict__ w2,
                                                      const float* __restrict__ b2) {
    __shared__ float w2s[HID * 256];
    __shared__ float b2s[256];
    __shared__ float roots[NODE_IN * HID];
    __shared__ float biass[HID];
    __shared__ float xs[NPB * NODE_IN];
    __shared__ float hs[NPB * HID];
    int tid = threadIdx.x;
    for (int i = tid; i < HID * 256; i += 256) w2s[i] = w2[i];
    b2s[tid] = b2[tid];
    roots[tid] = root1[tid];
    if (tid < HID) biass[tid] = bias1[tid];
    int nb = blockIdx.x * NPB;
    for (int idx = tid; idx < NPB * NODE_IN; idx += 256) {
        int n = nb + (idx >> 4);
        xs[idx] = (n < N_NODES) ? x[n * NODE_IN + (idx & 15)] : 0.f;
    }
    __syncthreads();

    int o = tid & 15;
    int nl0 = (tid >> 4) * NPT;

    #pragma unroll
    for (int j = 0; j < NPT; j++) {
        int n = nb + nl0 + j;
        float h = 0.f;
        if (n < N_NODES) {
            float inv = 1.f / fmaxf(g_cnt[n], 1.f);
            h = g_sum1[(long long)n * HID + o] * inv + biass[o];
            #pragma unroll
            for (int i = 0; i < NODE_IN; i++)
                h += xs[(nl0 + j) * NODE_IN + i] * roots[i * HID + o];
            h = fmaxf(h, 0.f);
            g_h1[(long long)n * HID + o] = h;
        }
        hs[(nl0 + j) * HID + o] = h;
    }
    __syncthreads();

    float hv[NPT][HID];
    #pragma unroll
    for (int j = 0; j < NPT; j++)
        #pragma unroll
        for (int i = 0; i < HID; i++)
            hv[j][i] = hs[(nl0 + j) * HID + i];

    #pragma unroll 1
    for (int k = 0; k < HID; k++) {
        float acc[NPT] = {0.f, 0.f, 0.f, 0.f};
        #pragma unroll
        for (int i = 0; i < HID; i++) {
            float w = w2s[k * 256 + i * 16 + o];
            #pragma unroll
            for (int j = 0; j < NPT; j++) acc[j] += hv[j][i] * w;
        }
        #pragma unroll
        for (int j = 0; j < NPT; j++) {
            int n = nb + nl0 + j;
            if (n < N_NODES) g_T[(long long)n * TROWP + k * 16 + o] = acc[j];
        }
    }
    {
        float acc[NPT] = {0.f, 0.f, 0.f, 0.f};
        #pragma unroll
        for (int i = 0; i < HID; i++) {
            float w = b2s[i * 16 + o];
            #pragma unroll
            for (int j = 0; j < NPT; j++) acc[j] += hv[j][i] * w;
        }
        #pragma unroll
        for (int j = 0; j < NPT; j++) {
            int n = nb + nl0 + j;
            if (n < N_NODES) g_T[(long long)n * TROWP + 256 + o] = acc[j];
        }
    }
}

// ---------------------------------------------------------------------------
// Layer-2 update + q head. One thread per node.
__global__ void __launch_bounds__(256) k_final(const float* __restrict__ root2,
                                               const float* __restrict__ bias2,
                                               const float* __restrict__ qw,
                                               const float* __restrict__ qb,
                                               float* __restrict__ out) {
    __shared__ float roots[HID * HID];
    __shared__ float biass[HID];
    __shared__ float qws[HID];
    int tid = threadIdx.x;
    roots[tid] = root2[tid];
    if (tid < HID) { biass[tid] = bias2[tid]; qws[tid] = qw[tid]; }
    __syncthreads();

    int n = blockIdx.x * 256 + tid;
    if (n >= N_NODES) return;
    float inv = 1.f / fmaxf(g_cnt[n], 1.f);
    float h1v[HID];
    const float4* h1p = (const float4*)&g_h1[(long long)n * HID];
    #pragma unroll
    for (int i = 0; i < HID / 4; i++) {
        float4 v = h1p[i];
        h1v[i * 4 + 0] = v.x; h1v[i * 4 + 1] = v.y;
        h1v[i * 4 + 2] = v.z; h1v[i * 4 + 3] = v.w;
    }
    float res = qb[0];
    #pragma unroll
    for (int o = 0; o < HID; o++) {
        float h2 = g_sum2[(long long)n * HID + o] * inv + biass[o];
        #pragma unroll
        for (int i = 0; i < HID; i++) h2 += h1v[i] * roots[i * HID + o];
        h2 = fmaxf(h2, 0.f);
        res += h2 * qws[o];
    }
    out[n] = res;
}

// ---------------------------------------------------------------------------
extern "C" void kernel_launch(void* const* d_in, const int* in_sizes, int n_in,
                              void* d_out, int out_size) {
    const float* x        = (const float*)d_in[0];
    const float* edge_attr= (const float*)d_in[1];
    const float* e1_w1    = (const float*)d_in[2];
    const float* e1_b1    = (const float*)d_in[3];
    const float* e1_w2    = (const float*)d_in[4];
    const float* e1_b2    = (const float*)d_in[5];
    const float* root1    = (const float*)d_in[6];
    const float* bias1    = (const float*)d_in[7];
    const float* e2_w1    = (const float*)d_in[8];
    const float* e2_b1    = (const float*)d_in[9];
    const float* e2_w2    = (const float*)d_in[10];
    const float* e2_b2    = (const float*)d_in[11];
    const float* root2    = (const float*)d_in[12];
    const float* bias2    = (const float*)d_in[13];
    const float* q_w      = (const float*)d_in[14];
    const float* q_b      = (const float*)d_in[15];
    const void*  eidx     = d_in[16];
    float* out = (float*)d_out;

    k_precompute<<<NODE_GRID, 256>>>(x, e1_w2, e1_b2, (const int*)eidx);
    k_edge<<<N_EDGES / 32, 256>>>(edge_attr, eidx, e1_w1, e1_b1, 1);
    k_update1_pre2<<<NODE_GRID, 256>>>(x, root1, bias1, e2_w2, e2_b2);
    k_edge<<<N_EDGES / 32, 256>>>(edge_attr, eidx, e2_w1, e2_b1, 2);
    k_final<<<(N_NODES + 255) / 256, 256>>>(root2, bias2, q_w, q_b, out);
}

// round 9
// speedup vs baseline: 1.6561x; 1.2326x over previous
#include <cuda_runtime.h>
#include <cuda_fp16.h>

#define N_NODES 50000
#define N_EDGES 400000
#define NODE_IN 16
#define EDGE_IN 8
#define HID 16
#define TROWP_H 320  // halves per node: 17x16 data + pad -> 640B = 5 cache lines
#define NPB 64       // nodes per block in node kernels
#define NPT 4        // nodes per thread
#define NODE_GRID ((N_NODES + NPB - 1) / NPB)  // 782

// Scratch (device globals: no allocation allowed)
__device__ __half g_Th[N_NODES * TROWP_H];  // factored tensor, fp16 (32 MB)
__device__ float g_sum1[N_NODES * HID];
__device__ float g_sum2[N_NODES * HID];
__device__ float g_cnt[N_NODES];
__device__ float g_h1[N_NODES * HID];
__device__ int   g_is64;

// ---------------------------------------------------------------------------
// Layer-1 per-node precompute: T[n][k][o] = sum_i x[n,i] * w2[k, i*16+o]
//                              T[n][16][o] = sum_i x[n,i] * b2[i*16+o]
// Fused: accumulator zeroing + edge_index width detection. Stores fp16.
__global__ void __launch_bounds__(256) k_precompute(const float* __restrict__ x,
                                                    const float* __restrict__ w2,
                                                    const float* __restrict__ b2,
                                                    const int* __restrict__ ei_raw) {
    __shared__ float w2s[HID * 256];
    __shared__ float b2s[256];
    __shared__ float xs[NPB * NODE_IN];
    int tid = threadIdx.x;
    int gid = blockIdx.x * 256 + tid;

    const int TOT = NODE_GRID * 256;
    for (int j = gid; j < N_NODES * HID; j += TOT) { g_sum1[j] = 0.f; g_sum2[j] = 0.f; }
    if (gid < N_NODES) g_cnt[gid] = 0.f;
    if (gid == 0) {
        int odd = 0;
        #pragma unroll
        for (int k = 0; k < 8; k++) odd |= ei_raw[2 * k + 1];
        g_is64 = (odd == 0) ? 1 : 0;
    }

    for (int i = tid; i < HID * 256; i += 256) w2s[i] = w2[i];
    b2s[tid] = b2[tid];
    int nb = blockIdx.x * NPB;
    for (int idx = tid; idx < NPB * NODE_IN; idx += 256) {
        int n = nb + (idx >> 4);
        xs[idx] = (n < N_NODES) ? x[n * NODE_IN + (idx & 15)] : 0.f;
    }
    __syncthreads();

    int o = tid & 15;
    int nl0 = (tid >> 4) * NPT;

    float xv[NPT][NODE_IN];
    #pragma unroll
    for (int j = 0; j < NPT; j++)
        #pragma unroll
        for (int i = 0; i < NODE_IN; i++)
            xv[j][i] = xs[(nl0 + j) * NODE_IN + i];

    #pragma unroll 1
    for (int k = 0; k < HID; k++) {
        float acc[NPT] = {0.f, 0.f, 0.f, 0.f};
        #pragma unroll
        for (int i = 0; i < NODE_IN; i++) {
            float w = w2s[k * 256 + i * 16 + o];
            #pragma unroll
            for (int j = 0; j < NPT; j++) acc[j] += xv[j][i] * w;
        }
        #pragma unroll
        for (int j = 0; j < NPT; j++) {
            int n = nb + nl0 + j;
            if (n < N_NODES) g_Th[(long long)n * TROWP_H + k * 16 + o] = __float2half_rn(acc[j]);
        }
    }
    {
        float acc[NPT] = {0.f, 0.f, 0.f, 0.f};
        #pragma unroll
        for (int i = 0; i < NODE_IN; i++) {
            float w = b2s[i * 16 + o];
            #pragma unroll
            for (int j = 0; j < NPT; j++) acc[j] += xv[j][i] * w;
        }
        #pragma unroll
        for (int j = 0; j < NPT; j++) {
            int n = nb + nl0 + j;
            if (n < N_NODES) g_Th[(long long)n * TROWP_H + 256 + o] = __float2half_rn(acc[j]);
        }
    }
}

// ---------------------------------------------------------------------------
// Edge pass, 8 lanes/edge, fp16 T, 5 x LDG.128 gather (640B/edge).
// Lane l in [0,8): uint4 load r holds halves m = r*64+l*8 .. +8, i.e.
// k = 4r + (l>>1), o = (l&1)*8 + j. Bias row (k=16) lives in r=4 for l<2.
// Fold across lane bits 1,2 (shfl_xor 2,4); lanes 0-3 each RED one o-quad.
// 256 threads = 32 edges/block. Grid 12500 (exact).
__global__ void __launch_bounds__(256) k_edge(const float* __restrict__ ea,
                                              const void* __restrict__ eidx,
                                              const float* __restrict__ w1,
                                              const float* __restrict__ b1,
                                              int layer) {
    __shared__ float w1s[EDGE_IN * HID];
    __shared__ float b1s[HID];
    int tid = threadIdx.x;
    if (tid < EDGE_IN * HID) w1s[tid] = w1[tid];
    if (tid < HID) b1s[tid] = b1[tid];
    __syncthreads();

    int lane = tid & 31;
    int l = lane & 7;
    int a = l >> 1;
    int base = lane & ~7;                // 8-lane group base within warp
    int e = blockIdx.x * 32 + (tid >> 5) * 4 + (lane >> 3);

    int src, dst;
    if (g_is64) {
        const long long* ei = (const long long*)eidx;
        src = (int)ei[e];
        dst = (int)ei[N_EDGES + e];
    } else {
        const int* ei = (const int*)eidx;
        src = ei[e];
        dst = ei[N_EDGES + e];
    }

    // edge MLP: every lane loads all 8 ea values (broadcast within group)
    const float4* eap = (const float4*)(ea + (long long)e * EDGE_IN);
    float4 a0 = eap[0], a1 = eap[1];
    float eav[EDGE_IN] = {a0.x, a0.y, a0.z, a0.w, a1.x, a1.y, a1.z, a1.w};
    float hA = b1s[l], hB = b1s[l + 8];
    #pragma unroll
    for (int i = 0; i < EDGE_IN; i++) {
        hA += eav[i] * w1s[i * HID + l];
        hB += eav[i] * w1s[i * HID + l + 8];
    }
    hA = fmaxf(hA, 0.f);
    hB = fmaxf(hB, 0.f);

    // gather fp16 T: 5 x LDG.128, one 128B line per (r, edge)
    const uint4* tp = (const uint4*)(g_Th + (long long)src * TROWP_H);
    uint4 t[5];
    #pragma unroll
    for (int r = 0; r < 5; r++) t[r] = tp[r * 8 + l];

    // this lane's 4 h values: k = a, 4+a, 8+a, 12+a
    float hk[4];
    hk[0] = __shfl_sync(0xffffffffu, hA, base + a);
    hk[1] = __shfl_sync(0xffffffffu, hA, base + 4 + a);
    hk[2] = __shfl_sync(0xffffffffu, hB, base + a);
    hk[3] = __shfl_sync(0xffffffffu, hB, base + 4 + a);

    float acc[8];
    if (l < 2) {                         // bias row (k=16) in t[4]
        const __half2* hp = (const __half2*)&t[4];
        #pragma unroll
        for (int q = 0; q < 4; q++) {
            float2 f = __half22float2(hp[q]);
            acc[2 * q] = f.x;
            acc[2 * q + 1] = f.y;
        }
    } else {
        #pragma unroll
        for (int j = 0; j < 8; j++) acc[j] = 0.f;
    }
    #pragma unroll
    for (int r = 0; r < 4; r++) {
        const __half2* hp = (const __half2*)&t[r];
        #pragma unroll
        for (int q = 0; q < 4; q++) {
            float2 f = __half22float2(hp[q]);
            acc[2 * q]     += hk[r] * f.x;
            acc[2 * q + 1] += hk[r] * f.y;
        }
    }

    // fold over a (lane bits 1,2): lanes of same parity sum their 4 k-groups
    #pragma unroll
    for (int j = 0; j < 8; j++) {
        acc[j] += __shfl_xor_sync(0xffffffffu, acc[j], 2);
        acc[j] += __shfl_xor_sync(0xffffffffu, acc[j], 4);
    }

    if (l < 4) {
        // lane 0 -> o 0-3 (acc 0-3), lane 2 -> o 4-7 (acc 4-7),
        // lane 1 -> o 8-11 (acc 0-3), lane 3 -> o 12-15 (acc 4-7)
        int o0 = (l & 1) * 8 + (l >> 1) * 4;
        int j0 = (l >> 1) * 4;
        float* sum_out = (layer == 1) ? g_sum1 : g_sum2;
        float* p = sum_out + (long long)dst * HID + o0;
        asm volatile("red.global.add.v4.f32 [%0], {%1, %2, %3, %4};"
                     :: "l"(p), "f"(acc[j0]), "f"(acc[j0 + 1]),
                        "f"(acc[j0 + 2]), "f"(acc[j0 + 3])
                     : "memory");
    }
    if (layer == 1 && l == 0) atomicAdd(&g_cnt[dst], 1.f);
}

// ---------------------------------------------------------------------------
// Layer-1 update (scatter-mean + root + bias + relu) fused with layer-2
// precompute of T (fp16) from h1.
__global__ void __launch_bounds__(256) k_update1_pre2(const float* __restrict__ x,
                                                      const float* __restrict__ root1,
                                                      const float* __restrict__ bias1,
                                                      const float* __restrict__ w2,
                                                      const float* __restrict__ b2) {
    __shared__ float w2s[HID * 256];
    __shared__ float b2s[256];
    __shared__ float roots[NODE_IN * HID];
    __shared__ float biass[HID];
    __shared__ float xs[NPB * NODE_IN];
    __shared__ float hs[NPB * HID];
    int tid = threadIdx.x;
    for (int i = tid; i < HID * 256; i += 256) w2s[i] = w2[i];
    b2s[tid] = b2[tid];
    roots[tid] = root1[tid];
    if (tid < HID) biass[tid] = bias1[tid];
    int nb = blockIdx.x * NPB;
    for (int idx = tid; idx < NPB * NODE_IN; idx += 256) {
        int n = nb + (idx >> 4);
        xs[idx] = (n < N_NODES) ? x[n * NODE_IN + (idx & 15)] : 0.f;
    }
    __syncthreads();

    int o = tid & 15;
    int nl0 = (tid >> 4) * NPT;

    #pragma unroll
    for (int j = 0; j < NPT; j++) {
        int n = nb + nl0 + j;
        float h = 0.f;
        if (n < N_NODES) {
            float inv = 1.f / fmaxf(g_cnt[n], 1.f);
            h = g_sum1[(long long)n * HID + o] * inv + biass[o];
            #pragma unroll
            for (int i = 0; i < NODE_IN; i++)
                h += xs[(nl0 + j) * NODE_IN + i] * roots[i * HID + o];
            h = fmaxf(h, 0.f);
            g_h1[(long long)n * HID + o] = h;
        }
        hs[(nl0 + j) * HID + o] = h;
    }
    __syncthreads();

    float hv[NPT][HID];
    #pragma unroll
    for (int j = 0; j < NPT; j++)
        #pragma unroll
        for (int i = 0; i < HID; i++)
            hv[j][i] = hs[(nl0 + j) * HID + i];

    #pragma unroll 1
    for (int k = 0; k < HID; k++) {
        float acc[NPT] = {0.f, 0.f, 0.f, 0.f};
        #pragma unroll
        for (int i = 0; i < HID; i++) {
            float w = w2s[k * 256 + i * 16 + o];
            #pragma unroll
            for (int j = 0; j < NPT; j++) acc[j] += hv[j][i] * w;
        }
        #pragma unroll
        for (int j = 0; j < NPT; j++) {
            int n = nb + nl0 + j;
            if (n < N_NODES) g_Th[(long long)n * TROWP_H + k * 16 + o] = __float2half_rn(acc[j]);
        }
    }
    {
        float acc[NPT] = {0.f, 0.f, 0.f, 0.f};
        #pragma unroll
        for (int i = 0; i < HID; i++) {
            float w = b2s[i * 16 + o];
            #pragma unroll
            for (int j = 0; j < NPT; j++) acc[j] += hv[j][i] * w;
        }
        #pragma unroll
        for (int j = 0; j < NPT; j++) {
            int n = nb + nl0 + j;
            if (n < N_NODES) g_Th[(long long)n * TROWP_H + 256 + o] = __float2half_rn(acc[j]);
        }
    }
}

// ---------------------------------------------------------------------------
// Layer-2 update + q head. One thread per node.
__global__ void __launch_bounds__(256) k_final(const float* __restrict__ root2,
                                               const float* __restrict__ bias2,
                                               const float* __restrict__ qw,
                                               const float* __restrict__ qb,
                                               float* __restrict__ out) {
    __shared__ float roots[HID * HID];
    __shared__ float biass[HID];
    __shared__ float qws[HID];
    int tid = threadIdx.x;
    roots[tid] = root2[tid];
    if (tid < HID) { biass[tid] = bias2[tid]; qws[tid] = qw[tid]; }
    __syncthreads();

    int n = blockIdx.x * 256 + tid;
    if (n >= N_NODES) return;
    float inv = 1.f / fmaxf(g_cnt[n], 1.f);
    float h1v[HID];
    const float4* h1p = (const float4*)&g_h1[(long long)n * HID];
    #pragma unroll
    for (int i = 0; i < HID / 4; i++) {
        float4 v = h1p[i];
        h1v[i * 4 + 0] = v.x; h1v[i * 4 + 1] = v.y;
        h1v[i * 4 + 2] = v.z; h1v[i * 4 + 3] = v.w;
    }
    float res = qb[0];
    #pragma unroll
    for (int o = 0; o < HID; o++) {
        float h2 = g_sum2[(long long)n * HID + o] * inv + biass[o];
        #pragma unroll
        for (int i = 0; i < HID; i++) h2 += h1v[i] * roots[i * HID + o];
        h2 = fmaxf(h2, 0.f);
        res += h2 * qws[o];
    }
    out[n] = res;
}

// ---------------------------------------------------------------------------
extern "C" void kernel_launch(void* const* d_in, const int* in_sizes, int n_in,
                              void* d_out, int out_size) {
    const float* x        = (const float*)d_in[0];
    const float* edge_attr= (const float*)d_in[1];
    const float* e1_w1    = (const float*)d_in[2];
    const float* e1_b1    = (const float*)d_in[3];
    const float* e1_w2    = (const float*)d_in[4];
    const float* e1_b2    = (const float*)d_in[5];
    const float* root1    = (const float*)d_in[6];
    const float* bias1    = (const float*)d_in[7];
    const float* e2_w1    = (const float*)d_in[8];
    const float* e2_b1    = (const float*)d_in[9];
    const float* e2_w2    = (const float*)d_in[10];
    const float* e2_b2    = (const float*)d_in[11];
    const float* root2    = (const float*)d_in[12];
    const float* bias2    = (const float*)d_in[13];
    const float* q_w      = (const float*)d_in[14];
    const float* q_b      = (const float*)d_in[15];
    const void*  eidx     = d_in[16];
    float* out = (float*)d_out;

    k_precompute<<<NODE_GRID, 256>>>(x, e1_w2, e1_b2, (const int*)eidx);
    k_edge<<<N_EDGES / 32, 256>>>(edge_attr, eidx, e1_w1, e1_b1, 1);
    k_update1_pre2<<<NODE_GRID, 256>>>(x, root1, bias1, e2_w2, e2_b2);
    k_edge<<<N_EDGES / 32, 256>>>(edge_attr, eidx, e2_w1, e2_b1, 2);
    k_final<<<(N_NODES + 255) / 256, 256>>>(root2, bias2, q_w, q_b, out);
}

// round 10
// speedup vs baseline: 1.7127x; 1.0342x over previous
#include <cuda_runtime.h>
#include <cuda_fp16.h>

#define N_NODES 50000
#define N_EDGES 400000
#define NODE_IN 16
#define EDGE_IN 8
#define HID 16
#define TROWP_H 320  // halves per node: 17x16 data + pad -> 640B = 5 cache lines
#define NPB 64       // nodes per block in node kernels
#define NODE_GRID ((N_NODES + NPB - 1) / NPB)  // 782

// Scratch (device globals: no allocation allowed)
__device__ __half g_Th[N_NODES * TROWP_H];  // factored tensor, fp16 (32 MB)
__device__ float g_sum1[N_NODES * HID];
__device__ float g_sum2[N_NODES * HID];
__device__ float g_cnt[N_NODES];
__device__ float g_h1[N_NODES * HID];
__device__ int   g_is64;

// f32x2 packed helpers (Blackwell packed fp32 pipe)
__device__ __forceinline__ unsigned long long pack_dup(float v) {
    unsigned long long r;
    asm("mov.b64 %0, {%1, %2};" : "=l"(r) : "f"(v), "f"(v));
    return r;
}
__device__ __forceinline__ unsigned long long pack2(float x, float y) {
    unsigned long long r;
    asm("mov.b64 %0, {%1, %2};" : "=l"(r) : "f"(x), "f"(y));
    return r;
}
__device__ __forceinline__ void unpack2(unsigned long long v, float& x, float& y) {
    asm("mov.b64 {%0, %1}, %2;" : "=f"(x), "=f"(y) : "l"(v));
}
#define FFMA2(acc, a, b) \
    asm("fma.rn.f32x2 %0, %1, %2, %0;" : "+l"(acc) : "l"(a), "l"(b))

// ---------------------------------------------------------------------------
// Layer-1 per-node precompute: T[n][k][o] = sum_i x[n,i] * w2[k, i*16+o]
//                              T[n][16][o] = sum_i x[n,i] * b2[i*16+o]
// Thread = (o-pair, 2 nodes): weight pair is a single LDS.64 (free pack),
// x dup-packed once in regs; inner op is fma.rn.f32x2. Stores half2.
// Fused: accumulator zeroing + edge_index width detection.
__global__ void __launch_bounds__(256) k_precompute(const float* __restrict__ x,
                                                    const float* __restrict__ w2,
                                                    const float* __restrict__ b2,
                                                    const int* __restrict__ ei_raw) {
    __shared__ __align__(16) float w2s[HID * 256];
    __shared__ __align__(16) float b2s[256];
    __shared__ __align__(16) float xs[NPB * NODE_IN];
    int tid = threadIdx.x;
    int gid = blockIdx.x * 256 + tid;

    const int TOT = NODE_GRID * 256;
    for (int j = gid; j < N_NODES * HID; j += TOT) { g_sum1[j] = 0.f; g_sum2[j] = 0.f; }
    if (gid < N_NODES) g_cnt[gid] = 0.f;
    if (gid == 0) {
        int odd = 0;
        #pragma unroll
        for (int k = 0; k < 8; k++) odd |= ei_raw[2 * k + 1];
        g_is64 = (odd == 0) ? 1 : 0;
    }

    for (int i = tid; i < HID * 256; i += 256) w2s[i] = w2[i];
    b2s[tid] = b2[tid];
    int nb = blockIdx.x * NPB;
    for (int idx = tid; idx < NPB * NODE_IN; idx += 256) {
        int n = nb + (idx >> 4);
        xs[idx] = (n < N_NODES) ? x[n * NODE_IN + (idx & 15)] : 0.f;
    }
    __syncthreads();

    int op = tid & 7;            // o-pair: o = 2*op, 2*op+1
    int nl0 = (tid >> 3) * 2;    // local node base (2 nodes per thread)

    unsigned long long xd[2][NODE_IN];
    #pragma unroll
    for (int j = 0; j < 2; j++)
        #pragma unroll
        for (int i = 0; i < NODE_IN; i++)
            xd[j][i] = pack_dup(xs[(nl0 + j) * NODE_IN + i]);

    int n0 = nb + nl0;
    #pragma unroll 1
    for (int k = 0; k < 17; k++) {
        const float* wrow = (k < 16) ? &w2s[k * 256] : b2s;
        unsigned long long a0 = 0ull, a1 = 0ull;
        #pragma unroll
        for (int i = 0; i < NODE_IN; i++) {
            unsigned long long wp =
                *(const unsigned long long*)&wrow[i * 16 + 2 * op];  // LDS.64
            FFMA2(a0, xd[0][i], wp);
            FFMA2(a1, xd[1][i], wp);
        }
        float lo, hi;
        unpack2(a0, lo, hi);
        if (n0 < N_NODES)
            *(__half2*)&g_Th[(long long)n0 * TROWP_H + k * 16 + 2 * op] =
                __floats2half2_rn(lo, hi);
        unpack2(a1, lo, hi);
        if (n0 + 1 < N_NODES)
            *(__half2*)&g_Th[(long long)(n0 + 1) * TROWP_H + k * 16 + 2 * op] =
                __floats2half2_rn(lo, hi);
    }
}

// ---------------------------------------------------------------------------
// Edge pass, 8 lanes/edge, fp16 T, 5 x LDG.128 gather (640B/edge).
// Lane l in [0,8): uint4 load r holds halves k = 4r + (l>>1), o = (l&1)*8 + j.
// Bias row (k=16) lives in r=4 for l<2.
// Fold: split-exchange xor-4 (keep own quad) then full xor-2 reduce -> 8 SHFL.
// Writers {0,1,4,5} each RED one o-quad. 256 threads = 32 edges/block.
__global__ void __launch_bounds__(256) k_edge(const float* __restrict__ ea,
                                              const void* __restrict__ eidx,
                                              const float* __restrict__ w1,
                                              const float* __restrict__ b1,
                                              int layer) {
    __shared__ float w1s[EDGE_IN * HID];
    __shared__ float b1s[HID];
    int tid = threadIdx.x;
    if (tid < EDGE_IN * HID) w1s[tid] = w1[tid];
    if (tid < HID) b1s[tid] = b1[tid];
    __syncthreads();

    int lane = tid & 31;
    int l = lane & 7;
    int a = l >> 1;
    int base = lane & ~7;                // 8-lane group base within warp
    int e = blockIdx.x * 32 + (tid >> 5) * 4 + (lane >> 3);

    int src, dst;
    if (g_is64) {
        const long long* ei = (const long long*)eidx;
        src = (int)ei[e];
        dst = (int)ei[N_EDGES + e];
    } else {
        const int* ei = (const int*)eidx;
        src = ei[e];
        dst = ei[N_EDGES + e];
    }

    // edge MLP: every lane loads all 8 ea values (broadcast within group)
    const float4* eap = (const float4*)(ea + (long long)e * EDGE_IN);
    float4 a0 = eap[0], a1 = eap[1];
    float eav[EDGE_IN] = {a0.x, a0.y, a0.z, a0.w, a1.x, a1.y, a1.z, a1.w};
    float hA = b1s[l], hB = b1s[l + 8];
    #pragma unroll
    for (int i = 0; i < EDGE_IN; i++) {
        hA += eav[i] * w1s[i * HID + l];
        hB += eav[i] * w1s[i * HID + l + 8];
    }
    hA = fmaxf(hA, 0.f);
    hB = fmaxf(hB, 0.f);

    // gather fp16 T: 5 x LDG.128, one 128B line per (r, edge)
    const uint4* tp = (const uint4*)(g_Th + (long long)src * TROWP_H);
    uint4 t[5];
    #pragma unroll
    for (int r = 0; r < 5; r++) t[r] = tp[r * 8 + l];

    // this lane's 4 h values: k = a, 4+a, 8+a, 12+a
    float hk[4];
    hk[0] = __shfl_sync(0xffffffffu, hA, base + a);
    hk[1] = __shfl_sync(0xffffffffu, hA, base + 4 + a);
    hk[2] = __shfl_sync(0xffffffffu, hB, base + a);
    hk[3] = __shfl_sync(0xffffffffu, hB, base + 4 + a);

    float acc[8];
    if (l < 2) {                         // bias row (k=16) in t[4]
        const __half2* hp = (const __half2*)&t[4];
        #pragma unroll
        for (int q = 0; q < 4; q++) {
            float2 f = __half22float2(hp[q]);
            acc[2 * q] = f.x;
            acc[2 * q + 1] = f.y;
        }
    } else {
        #pragma unroll
        for (int j = 0; j < 8; j++) acc[j] = 0.f;
    }
    #pragma unroll
    for (int r = 0; r < 4; r++) {
        const __half2* hp = (const __half2*)&t[r];
        #pragma unroll
        for (int q = 0; q < 4; q++) {
            float2 f = __half22float2(hp[q]);
            acc[2 * q]     += hk[r] * f.x;
            acc[2 * q + 1] += hk[r] * f.y;
        }
    }

    // fold over a (4 lanes per parity): split-exchange then reduce -> 8 SHFL
    int s = (l >> 2) & 1;                // which quad this lane keeps
    float res[4];
    #pragma unroll
    for (int j = 0; j < 4; j++) {
        float send = s ? acc[j] : acc[j + 4];
        float got = __shfl_xor_sync(0xffffffffu, send, 4);
        res[j] = (s ? acc[j + 4] : acc[j]) + got;
    }
    #pragma unroll
    for (int j = 0; j < 4; j++)
        res[j] += __shfl_xor_sync(0xffffffffu, res[j], 2);

    if ((l & 2) == 0) {                  // writers: l in {0,1,4,5}
        // o0 = parity*8 + kept-quad*4
        int o0 = (l & 1) * 8 + (l >> 2) * 4;
        float* sum_out = (layer == 1) ? g_sum1 : g_sum2;
        float* p = sum_out + (long long)dst * HID + o0;
        asm volatile("red.global.add.v4.f32 [%0], {%1, %2, %3, %4};"
                     :: "l"(p), "f"(res[0]), "f"(res[1]),
                        "f"(res[2]), "f"(res[3])
                     : "memory");
    }
    if (layer == 1 && l == 0) atomicAdd(&g_cnt[dst], 1.f);
}

// ---------------------------------------------------------------------------
// Layer-1 update (scatter-mean + root + bias + relu) fused with layer-2
// precompute of T (fp16) from h1. Same o-pair / LDS.64 / f32x2 structure.
__global__ void __launch_bounds__(256) k_update1_pre2(const float* __restrict__ x,
                                                      const float* __restrict__ root1,
                                                      const float* __restrict__ bias1,
                                                      const float* __restrict__ w2,
                                                      const float* __restrict__ b2) {
    __shared__ __align__(16) float w2s[HID * 256];
    __shared__ __align__(16) float b2s[256];
    __shared__ __align__(16) float roots[NODE_IN * HID];
    __shared__ __align__(16) float biass[HID];
    __shared__ __align__(16) float xs[NPB * NODE_IN];
    __shared__ __align__(16) float hs[NPB * HID];
    int tid = threadIdx.x;
    for (int i = tid; i < HID * 256; i += 256) w2s[i] = w2[i];
    b2s[tid] = b2[tid];
    roots[tid] = root1[tid];
    if (tid < HID) biass[tid] = bias1[tid];
    int nb = blockIdx.x * NPB;
    for (int idx = tid; idx < NPB * NODE_IN; idx += 256) {
        int n = nb + (idx >> 4);
        xs[idx] = (n < N_NODES) ? x[n * NODE_IN + (idx & 15)] : 0.f;
    }
    __syncthreads();

    int op = tid & 7;
    int nl0 = (tid >> 3) * 2;
    int n0 = nb + nl0;

    // stage 1: layer-1 node update for 2 nodes x o-pair
    {
        unsigned long long xd[2][NODE_IN];
        #pragma unroll
        for (int j = 0; j < 2; j++)
            #pragma unroll
            for (int i = 0; i < NODE_IN; i++)
                xd[j][i] = pack_dup(xs[(nl0 + j) * NODE_IN + i]);

        #pragma unroll
        for (int j = 0; j < 2; j++) {
            int n = n0 + j;
            float rx = 0.f, ry = 0.f;
            if (n < N_NODES) {
                float inv = 1.f / fmaxf(g_cnt[n], 1.f);
                float2 sm = *(const float2*)&g_sum1[(long long)n * HID + 2 * op];
                unsigned long long acc =
                    pack2(sm.x * inv + biass[2 * op], sm.y * inv + biass[2 * op + 1]);
                #pragma unroll
                for (int i = 0; i < NODE_IN; i++) {
                    unsigned long long rp =
                        *(const unsigned long long*)&roots[i * 16 + 2 * op];
                    FFMA2(acc, xd[j][i], rp);
                }
                unpack2(acc, rx, ry);
                rx = fmaxf(rx, 0.f);
                ry = fmaxf(ry, 0.f);
                *(float2*)&g_h1[(long long)n * HID + 2 * op] = make_float2(rx, ry);
            }
            *(float2*)&hs[(nl0 + j) * HID + 2 * op] = make_float2(rx, ry);
        }
    }
    __syncthreads();

    // stage 2: layer-2 T precompute from h1
    unsigned long long hd[2][HID];
    #pragma unroll
    for (int j = 0; j < 2; j++)
        #pragma unroll
        for (int i = 0; i < HID; i++)
            hd[j][i] = pack_dup(hs[(nl0 + j) * HID + i]);

    #pragma unroll 1
    for (int k = 0; k < 17; k++) {
        const float* wrow = (k < 16) ? &w2s[k * 256] : b2s;
        unsigned long long a0 = 0ull, a1 = 0ull;
        #pragma unroll
        for (int i = 0; i < HID; i++) {
            unsigned long long wp =
                *(const unsigned long long*)&wrow[i * 16 + 2 * op];
            FFMA2(a0, hd[0][i], wp);
            FFMA2(a1, hd[1][i], wp);
        }
        float lo, hi;
        unpack2(a0, lo, hi);
        if (n0 < N_NODES)
            *(__half2*)&g_Th[(long long)n0 * TROWP_H + k * 16 + 2 * op] =
                __floats2half2_rn(lo, hi);
        unpack2(a1, lo, hi);
        if (n0 + 1 < N_NODES)
            *(__half2*)&g_Th[(long long)(n0 + 1) * TROWP_H + k * 16 + 2 * op] =
                __floats2half2_rn(lo, hi);
    }
}

// ---------------------------------------------------------------------------
// Layer-2 update + q head. One thread per node.
__global__ void __launch_bounds__(256) k_final(const float* __restrict__ root2,
                                               const float* __restrict__ bias2,
                                               const float* __restrict__ qw,
                                               const float* __restrict__ qb,
                                               float* __restrict__ out) {
    __shared__ float roots[HID * HID];
    __shared__ float biass[HID];
    __shared__ float qws[HID];
    int tid = threadIdx.x;
    roots[tid] = root2[tid];
    if (tid < HID) { biass[tid] = bias2[tid]; qws[tid] = qw[tid]; }
    __syncthreads();

    int n = blockIdx.x * 256 + tid;
    if (n >= N_NODES) return;
    float inv = 1.f / fmaxf(g_cnt[n], 1.f);
    float h1v[HID];
    const float4* h1p = (const float4*)&g_h1[(long long)n * HID];
    #pragma unroll
    for (int i = 0; i < HID / 4; i++) {
        float4 v = h1p[i];
        h1v[i * 4 + 0] = v.x; h1v[i * 4 + 1] = v.y;
        h1v[i * 4 + 2] = v.z; h1v[i * 4 + 3] = v.w;
    }
    float res = qb[0];
    #pragma unroll
    for (int o = 0; o < HID; o++) {
        float h2 = g_sum2[(long long)n * HID + o] * inv + biass[o];
        #pragma unroll
        for (int i = 0; i < HID; i++) h2 += h1v[i] * roots[i * HID + o];
        h2 = fmaxf(h2, 0.f);
        res += h2 * qws[o];
    }
    out[n] = res;
}

// ---------------------------------------------------------------------------
extern "C" void kernel_launch(void* const* d_in, const int* in_sizes, int n_in,
                              void* d_out, int out_size) {
    const float* x        = (const float*)d_in[0];
    const float* edge_attr= (const float*)d_in[1];
    const float* e1_w1    = (const float*)d_in[2];
    const float* e1_b1    = (const float*)d_in[3];
    const float* e1_w2    = (const float*)d_in[4];
    const float* e1_b2    = (const float*)d_in[5];
    const float* root1    = (const float*)d_in[6];
    const float* bias1    = (const float*)d_in[7];
    const float* e2_w1    = (const float*)d_in[8];
    const float* e2_b1    = (const float*)d_in[9];
    const float* e2_w2    = (const float*)d_in[10];
    const float* e2_b2    = (const float*)d_in[11];
    const float* root2    = (const float*)d_in[12];
    const float* bias2    = (const float*)d_in[13];
    const float* q_w      = (const float*)d_in[14];
    const float* q_b      = (const float*)d_in[15];
    const void*  eidx     = d_in[16];
    float* out = (float*)d_out;

    k_precompute<<<NODE_GRID, 256>>>(x, e1_w2, e1_b2, (const int*)eidx);
    k_edge<<<N_EDGES / 32, 256>>>(edge_attr, eidx, e1_w1, e1_b1, 1);
    k_update1_pre2<<<NODE_GRID, 256>>>(x, root1, bias1, e2_w2, e2_b2);
    k_edge<<<N_EDGES / 32, 256>>>(edge_attr, eidx, e2_w1, e2_b1, 2);
    k_final<<<(N_NODES + 255) / 256, 256>>>(root2, bias2, q_w, q_b, out);
}

// round 12
// speedup vs baseline: 1.7441x; 1.0184x over previous
#include <cuda_runtime.h>
#include <cuda_fp16.h>

#define N_NODES 50000
#define N_EDGES 400000
#define NODE_IN 16
#define EDGE_IN 8
#define HID 16
#define TROWP_H 320  // halves per node: 17x16 data + pad -> 640B = 5 cache lines
#define NPB 64       // nodes per block in node kernels
#define NODE_GRID ((N_NODES + NPB - 1) / NPB)  // 782

// Scratch (device globals: no allocation allowed)
__device__ __half g_Th[N_NODES * TROWP_H];  // factored tensor, fp16 (32 MB)
__device__ float g_sum1[N_NODES * HID];
__device__ float g_sum2[N_NODES * HID];
__device__ float g_cnt[N_NODES];
__device__ float g_h1[N_NODES * HID];
__device__ int   g_is64;

// f32x2 packed helpers (Blackwell packed fp32 pipe)
__device__ __forceinline__ unsigned long long pack_dup(float v) {
    unsigned long long r;
    asm("mov.b64 %0, {%1, %2};" : "=l"(r) : "f"(v), "f"(v));
    return r;
}
__device__ __forceinline__ unsigned long long pack2(float x, float y) {
    unsigned long long r;
    asm("mov.b64 %0, {%1, %2};" : "=l"(r) : "f"(x), "f"(y));
    return r;
}
__device__ __forceinline__ void unpack2(unsigned long long v, float& x, float& y) {
    asm("mov.b64 {%0, %1}, %2;" : "=f"(x), "=f"(y) : "l"(v));
}
#define FFMA2(acc, a, b) \
    asm("fma.rn.f32x2 %0, %1, %2, %0;" : "+l"(acc) : "l"(a), "l"(b))

// ---------------------------------------------------------------------------
// Layer-1 per-node precompute: T[n][k][o] = sum_i x[n,i] * w2[k, i*16+o]
//                              T[n][16][o] = sum_i x[n,i] * b2[i*16+o]
// Thread = (o-pair, 2 nodes); LDS.64 weight pairs; fma.rn.f32x2 inner op.
// Fused: accumulator zeroing + edge_index width detection.
__global__ void __launch_bounds__(256) k_precompute(const float* __restrict__ x,
                                                    const float* __restrict__ w2,
                                                    const float* __restrict__ b2,
                                                    const int* __restrict__ ei_raw) {
    __shared__ __align__(16) float w2s[HID * 256];
    __shared__ __align__(16) float b2s[256];
    __shared__ __align__(16) float xs[NPB * NODE_IN];
    int tid = threadIdx.x;
    int gid = blockIdx.x * 256 + tid;

    const int TOT = NODE_GRID * 256;
    for (int j = gid; j < N_NODES * HID; j += TOT) { g_sum1[j] = 0.f; g_sum2[j] = 0.f; }
    if (gid < N_NODES) g_cnt[gid] = 0.f;
    if (gid == 0) {
        int odd = 0;
        #pragma unroll
        for (int k = 0; k < 8; k++) odd |= ei_raw[2 * k + 1];
        g_is64 = (odd == 0) ? 1 : 0;
    }

    for (int i = tid; i < HID * 256; i += 256) w2s[i] = w2[i];
    b2s[tid] = b2[tid];
    int nb = blockIdx.x * NPB;
    for (int idx = tid; idx < NPB * NODE_IN; idx += 256) {
        int n = nb + (idx >> 4);
        xs[idx] = (n < N_NODES) ? x[n * NODE_IN + (idx & 15)] : 0.f;
    }
    __syncthreads();

    int op = tid & 7;            // o-pair: o = 2*op, 2*op+1
    int nl0 = (tid >> 3) * 2;    // local node base (2 nodes per thread)

    unsigned long long xd[2][NODE_IN];
    #pragma unroll
    for (int j = 0; j < 2; j++)
        #pragma unroll
        for (int i = 0; i < NODE_IN; i++)
            xd[j][i] = pack_dup(xs[(nl0 + j) * NODE_IN + i]);

    int n0 = nb + nl0;
    #pragma unroll 1
    for (int k = 0; k < 17; k++) {
        const float* wrow = (k < 16) ? &w2s[k * 256] : b2s;
        unsigned long long a0 = 0ull, a1 = 0ull;
        #pragma unroll
        for (int i = 0; i < NODE_IN; i++) {
            unsigned long long wp =
                *(const unsigned long long*)&wrow[i * 16 + 2 * op];  // LDS.64
            FFMA2(a0, xd[0][i], wp);
            FFMA2(a1, xd[1][i], wp);
        }
        float lo, hi;
        unpack2(a0, lo, hi);
        if (n0 < N_NODES)
            *(__half2*)&g_Th[(long long)n0 * TROWP_H + k * 16 + 2 * op] =
                __floats2half2_rn(lo, hi);
        unpack2(a1, lo, hi);
        if (n0 + 1 < N_NODES)
            *(__half2*)&g_Th[(long long)(n0 + 1) * TROWP_H + k * 16 + 2 * op] =
                __floats2half2_rn(lo, hi);
    }
}

// ---------------------------------------------------------------------------
// Edge pass, 8 lanes/edge, fp16 T, 5 x LDG.128 gather (640B/edge).
// Lane l in [0,8): uint4 load r holds halves k = 4r + (l>>1), o = (l&1)*8 + j.
// Bias row (k=16) lives in r=4 for l<2.
// Contraction in packed fp16 (HFMA2, 4-term chains) — no per-element F2F.
// h packed as half2 (hA,hB): one SHFL moves both; PRMT dups build hk half2s.
// Fold: split-exchange xor-4 then xor-2 reduce in fp32 -> 8 SHFL.
// Writers {0,1,4,5} each RED one o-quad. 256 threads = 32 edges/block.
__global__ void __launch_bounds__(256) k_edge(const float* __restrict__ ea,
                                              const void* __restrict__ eidx,
                                              const float* __restrict__ w1,
                                              const float* __restrict__ b1,
                                              int layer) {
    __shared__ float w1s[EDGE_IN * HID];
    __shared__ float b1s[HID];
    int tid = threadIdx.x;
    if (tid < EDGE_IN * HID) w1s[tid] = w1[tid];
    if (tid < HID) b1s[tid] = b1[tid];
    __syncthreads();

    int lane = tid & 31;
    int l = lane & 7;
    int a = l >> 1;
    int base = lane & ~7;                // 8-lane group base within warp
    int e = blockIdx.x * 32 + (tid >> 5) * 4 + (lane >> 3);

    int src, dst;
    if (g_is64) {
        const long long* ei = (const long long*)eidx;
        src = (int)ei[e];
        dst = (int)ei[N_EDGES + e];
    } else {
        const int* ei = (const int*)eidx;
        src = ei[e];
        dst = ei[N_EDGES + e];
    }

    // edge MLP: every lane loads all 8 ea values (broadcast within group)
    const float4* eap = (const float4*)(ea + (long long)e * EDGE_IN);
    float4 a0 = eap[0], a1 = eap[1];
    float eav[EDGE_IN] = {a0.x, a0.y, a0.z, a0.w, a1.x, a1.y, a1.z, a1.w};
    float hA = b1s[l], hB = b1s[l + 8];
    #pragma unroll
    for (int i = 0; i < EDGE_IN; i++) {
        hA += eav[i] * w1s[i * HID + l];
        hB += eav[i] * w1s[i * HID + l + 8];
    }
    hA = fmaxf(hA, 0.f);
    hB = fmaxf(hB, 0.f);

    // gather fp16 T: 5 x LDG.128, one 128B line per (r, edge)
    const uint4* tp = (const uint4*)(g_Th + (long long)src * TROWP_H);
    uint4 t[5];
    #pragma unroll
    for (int r = 0; r < 5; r++) t[r] = tp[r * 8 + l];

    // pack (hA,hB) -> half2; one shuffle moves both h values
    __half2 hpk = __floats2half2_rn(hA, hB);
    unsigned int hbits = *(unsigned int*)&hpk;
    unsigned int u0 = __shfl_sync(0xffffffffu, hbits, base + a);      // (h[a], h[8+a])
    unsigned int u1 = __shfl_sync(0xffffffffu, hbits, base + 4 + a);  // (h[4+a], h[12+a])
    __half2 h2_0 = *(__half2*)&u0;
    __half2 h2_1 = *(__half2*)&u1;
    // dup half2 for the 4 k values r=0..3 -> k = 4r + (l>>1)
    __half2 hd[4];
    hd[0] = __low2half2(h2_0);   // h[a]
    hd[1] = __low2half2(h2_1);   // h[4+a]
    hd[2] = __high2half2(h2_0);  // h[8+a]
    hd[3] = __high2half2(h2_1);  // h[12+a]

    // fp16 packed contraction: 4-term HFMA2 chains per o-pair
    __half2 acc2[4];
    if (l < 2) {                         // bias row (k=16) in t[4]
        const __half2* bp = (const __half2*)&t[4];
        #pragma unroll
        for (int q = 0; q < 4; q++) acc2[q] = bp[q];
    } else {
        __half2 z = __floats2half2_rn(0.f, 0.f);
        #pragma unroll
        for (int q = 0; q < 4; q++) acc2[q] = z;
    }
    #pragma unroll
    for (int r = 0; r < 4; r++) {
        const __half2* hp = (const __half2*)&t[r];
        #pragma unroll
        for (int q = 0; q < 4; q++)
            acc2[q] = __hfma2(hd[r], hp[q], acc2[q]);
    }

    // convert 4 half2 accs -> 8 fp32 (only 8 F2F per lane)
    float acc[8];
    #pragma unroll
    for (int q = 0; q < 4; q++) {
        float2 f = __half22float2(acc2[q]);
        acc[2 * q] = f.x;
        acc[2 * q + 1] = f.y;
    }

    // fold over a (4 lanes per parity): split-exchange then reduce -> 8 SHFL
    int s = (l >> 2) & 1;                // which quad this lane keeps
    float res[4];
    #pragma unroll
    for (int j = 0; j < 4; j++) {
        float send = s ? acc[j] : acc[j + 4];
        float got = __shfl_xor_sync(0xffffffffu, send, 4);
        res[j] = (s ? acc[j + 4] : acc[j]) + got;
    }
    #pragma unroll
    for (int j = 0; j < 4; j++)
        res[j] += __shfl_xor_sync(0xffffffffu, res[j], 2);

    if ((l & 2) == 0) {                  // writers: l in {0,1,4,5}
        // o0 = parity*8 + kept-quad*4
        int o0 = (l & 1) * 8 + (l >> 2) * 4;
        float* sum_out = (layer == 1) ? g_sum1 : g_sum2;
        float* p = sum_out + (long long)dst * HID + o0;
        asm volatile("red.global.add.v4.f32 [%0], {%1, %2, %3, %4};"
                     :: "l"(p), "f"(res[0]), "f"(res[1]),
                        "f"(res[2]), "f"(res[3])
                     : "memory");
    }
    if (layer == 1 && l == 0) atomicAdd(&g_cnt[dst], 1.f);
}

// ---------------------------------------------------------------------------
// Layer-1 update (scatter-mean + root + bias + relu) fused with layer-2
// precompute of T (fp16) from h1. o-pair / LDS.64 / f32x2 structure.
__global__ void __launch_bounds__(256) k_update1_pre2(const float* __restrict__ x,
                                                      const float* __restrict__ root1,
                                                      const float* __restrict__ bias1,
                                                      const float* __restrict__ w2,
                                                      const float* __restrict__ b2) {
    __shared__ __align__(16) float w2s[HID * 256];
    __shared__ __align__(16) float b2s[256];
    __shared__ __align__(16) float roots[NODE_IN * HID];
    __shared__ __align__(16) float biass[HID];
    __shared__ __align__(16) float xs[NPB * NODE_IN];
    __shared__ __align__(16) float hs[NPB * HID];
    int tid = threadIdx.x;
    for (int i = tid; i < HID * 256; i += 256) w2s[i] = w2[i];
    b2s[tid] = b2[tid];
    roots[tid] = root1[tid];
    if (tid < HID) biass[tid] = bias1[tid];
    int nb = blockIdx.x * NPB;
    for (int idx = tid; idx < NPB * NODE_IN; idx += 256) {
        int n = nb + (idx >> 4);
        xs[idx] = (n < N_NODES) ? x[n * NODE_IN + (idx & 15)] : 0.f;
    }
    __syncthreads();

    int op = tid & 7;
    int nl0 = (tid >> 3) * 2;
    int n0 = nb + nl0;

    // stage 1: layer-1 node update for 2 nodes x o-pair
    {
        unsigned long long xd[2][NODE_IN];
        #pragma unroll
        for (int j = 0; j < 2; j++)
            #pragma unroll
            for (int i = 0; i < NODE_IN; i++)
                xd[j][i] = pack_dup(xs[(nl0 + j) * NODE_IN + i]);

        #pragma unroll
        for (int j = 0; j < 2; j++) {
            int n = n0 + j;
            float rx = 0.f, ry = 0.f;
            if (n < N_NODES) {
                float inv = 1.f / fmaxf(g_cnt[n], 1.f);
                float2 sm = *(const float2*)&g_sum1[(long long)n * HID + 2 * op];
                unsigned long long acc =
                    pack2(sm.x * inv + biass[2 * op], sm.y * inv + biass[2 * op + 1]);
                #pragma unroll
                for (int i = 0; i < NODE_IN; i++) {
                    unsigned long long rp =
                        *(const unsigned long long*)&roots[i * 16 + 2 * op];
                    FFMA2(acc, xd[j][i], rp);
                }
                unpack2(acc, rx, ry);
                rx = fmaxf(rx, 0.f);
                ry = fmaxf(ry, 0.f);
                *(float2*)&g_h1[(long long)n * HID + 2 * op] = make_float2(rx, ry);
            }
            *(float2*)&hs[(nl0 + j) * HID + 2 * op] = make_float2(rx, ry);
        }
    }
    __syncthreads();

    // stage 2: layer-2 T precompute from h1
    unsigned long long hd[2][HID];
    #pragma unroll
    for (int j = 0; j < 2; j++)
        #pragma unroll
        for (int i = 0; i < HID; i++)
            hd[j][i] = pack_dup(hs[(nl0 + j) * HID + i]);

    #pragma unroll 1
    for (int k = 0; k < 17; k++) {
        const float* wrow = (k < 16) ? &w2s[k * 256] : b2s;
        unsigned long long a0 = 0ull, a1 = 0ull;
        #pragma unroll
        for (int i = 0; i < HID; i++) {
            unsigned long long wp =
                *(const unsigned long long*)&wrow[i * 16 + 2 * op];
            FFMA2(a0, hd[0][i], wp);
            FFMA2(a1, hd[1][i], wp);
        }
        float lo, hi;
        unpack2(a0, lo, hi);
        if (n0 < N_NODES)
            *(__half2*)&g_Th[(long long)n0 * TROWP_H + k * 16 + 2 * op] =
                __floats2half2_rn(lo, hi);
        unpack2(a1, lo, hi);
        if (n0 + 1 < N_NODES)
            *(__half2*)&g_Th[(long long)(n0 + 1) * TROWP_H + k * 16 + 2 * op] =
                __floats2half2_rn(lo, hi);
    }
}

// ---------------------------------------------------------------------------
// Layer-2 update + q head. One thread per node.
__global__ void __launch_bounds__(256) k_final(const float* __restrict__ root2,
                                               const float* __restrict__ bias2,
                                               const float* __restrict__ qw,
                                               const float* __restrict__ qb,
                                               float* __restrict__ out) {
    __shared__ float roots[HID * HID];
    __shared__ float biass[HID];
    __shared__ float qws[HID];
    int tid = threadIdx.x;
    roots[tid] = root2[tid];
    if (tid < HID) { biass[tid] = bias2[tid]; qws[tid] = qw[tid]; }
    __syncthreads();

    int n = blockIdx.x * 256 + tid;
    if (n >= N_NODES) return;
    float inv = 1.f / fmaxf(g_cnt[n], 1.f);
    float h1v[HID];
    const float4* h1p = (const float4*)&g_h1[(long long)n * HID];
    #pragma unroll
    for (int i = 0; i < HID / 4; i++) {
        float4 v = h1p[i];
        h1v[i * 4 + 0] = v.x; h1v[i * 4 + 1] = v.y;
        h1v[i * 4 + 2] = v.z; h1v[i * 4 + 3] = v.w;
    }
    float res = qb[0];
    #pragma unroll
    for (int o = 0; o < HID; o++) {
        float h2 = g_sum2[(long long)n * HID + o] * inv + biass[o];
        #pragma unroll
        for (int i = 0; i < HID; i++) h2 += h1v[i] * roots[i * HID + o];
        h2 = fmaxf(h2, 0.f);
        res += h2 * qws[o];
    }
    out[n] = res;
}

// ---------------------------------------------------------------------------
extern "C" void kernel_launch(void* const* d_in, const int* in_sizes, int n_in,
                              void* d_out, int out_size) {
    const float* x        = (const float*)d_in[0];
    const float* edge_attr= (const float*)d_in[1];
    const float* e1_w1    = (const float*)d_in[2];
    const float* e1_b1    = (const float*)d_in[3];
    const float* e1_w2    = (const float*)d_in[4];
    const float* e1_b2    = (const float*)d_in[5];
    const float* root1    = (const float*)d_in[6];
    const float* bias1    = (const float*)d_in[7];
    const float* e2_w1    = (const float*)d_in[8];
    const float* e2_b1    = (const float*)d_in[9];
    const float* e2_w2    = (const float*)d_in[10];
    const float* e2_b2    = (const float*)d_in[11];
    const float* root2    = (const float*)d_in[12];
    const float* bias2    = (const float*)d_in[13];
    const float* q_w      = (const float*)d_in[14];
    const float* q_b      = (const float*)d_in[15];
    const void*  eidx     = d_in[16];
    float* out = (float*)d_out;

    k_precompute<<<NODE_GRID, 256>>>(x, e1_w2, e1_b2, (const int*)eidx);
    k_edge<<<N_EDGES / 32, 256>>>(edge_attr, eidx, e1_w1, e1_b1, 1);
    k_update1_pre2<<<NODE_GRID, 256>>>(x, root1, bias1, e2_w2, e2_b2);
    k_edge<<<N_EDGES / 32, 256>>>(edge_attr, eidx, e2_w1, e2_b1, 2);
    k_final<<<(N_NODES + 255) / 256, 256>>>(root2, bias2, q_w, q_b, out);
}

// round 14
// speedup vs baseline: 1.7963x; 1.0299x over previous
#include <cuda_runtime.h>
#include <cuda_fp16.h>

#define N_NODES 50000
#define N_EDGES 400000
#define NODE_IN 16
#define EDGE_IN 8
#define HID 16
#define TROWP_H 320  // halves per node in gmem: 17x16 + pad -> 640B = 5 lines
#define NPB 40       // nodes per block in node kernels (50000 = 1250*40 exact)
#define NTH 160      // threads: 8 o-pairs x 20 node-pairs
#define NODE_GRID 1250
#define SROW 328     // halves per node row in smem tile (656B, bank-spread pad)

// Scratch (device globals: no allocation allowed)
__device__ __half g_Th[N_NODES * TROWP_H];  // factored tensor, fp16 (32 MB)
__device__ float g_sum1[N_NODES * HID];
__device__ float g_sum2[N_NODES * HID];
__device__ float g_cnt[N_NODES];
__device__ float g_h1[N_NODES * HID];
__device__ int   g_is64;

// f32x2 packed helpers (Blackwell packed fp32 pipe)
__device__ __forceinline__ unsigned long long pack_dup(float v) {
    unsigned long long r;
    asm("mov.b64 %0, {%1, %2};" : "=l"(r) : "f"(v), "f"(v));
    return r;
}
__device__ __forceinline__ unsigned long long pack2(float x, float y) {
    unsigned long long r;
    asm("mov.b64 %0, {%1, %2};" : "=l"(r) : "f"(x), "f"(y));
    return r;
}
__device__ __forceinline__ void unpack2(unsigned long long v, float& x, float& y) {
    asm("mov.b64 {%0, %1}, %2;" : "=f"(x), "=f"(y) : "l"(v));
}
#define FFMA2(acc, a, b) \
    asm("fma.rn.f32x2 %0, %1, %2, %0;" : "+l"(acc) : "l"(a), "l"(b))

// Coalesced writeout of the staged T tile: NPB*640B as uint4, 10 per thread.
__device__ __forceinline__ void tile_writeout(const __half* Tst, int nb, int tid) {
    const char* sbase = (const char*)Tst;
    char* gbase = (char*)(g_Th + (long long)nb * TROWP_H);
    #pragma unroll
    for (int j = 0; j < 10; j++) {
        int idx = tid + j * NTH;         // 0..1599 uint4 slots
        int node = idx / 40;
        int w16 = idx % 40;              // 16B chunk within node row
        uint4 v = *(const uint4*)(sbase + node * 656 + w16 * 16);
        *(uint4*)(gbase + node * 640 + w16 * 16) = v;
    }
}

// ---------------------------------------------------------------------------
// Layer-1 per-node precompute: T[n][k][o] = sum_i x[n,i] * w2[k, i*16+o]
//                              row 16     = sum_i x[n,i] * b2[i*16+o]
// Thread = (o-pair, 2 nodes); LDS.64 weight pairs; fma.rn.f32x2 inner op.
// T staged in smem (conflict-free STS), written out coalesced as uint4.
// Fused: accumulator zeroing + edge_index width detection.
__global__ void __launch_bounds__(NTH) k_precompute(const float* __restrict__ x,
                                                    const float* __restrict__ w2,
                                                    const float* __restrict__ b2,
                                                    const int* __restrict__ ei_raw) {
    __shared__ __align__(16) float w2s[17 * 256];   // rows 0-15: w2, row 16: b2
    __shared__ __align__(16) __half Tst[NPB * SROW];
    int tid = threadIdx.x;
    int gid = blockIdx.x * NTH + tid;

    // fused zeroing of accumulators (kernel boundary orders vs. edge pass)
    const int TOT = NODE_GRID * NTH;    // 200000
    for (int j = gid; j < N_NODES * HID; j += TOT) { g_sum1[j] = 0.f; g_sum2[j] = 0.f; }
    if (gid < N_NODES) g_cnt[gid] = 0.f;
    if (gid == 0) {
        int odd = 0;
        #pragma unroll
        for (int k = 0; k < 8; k++) odd |= ei_raw[2 * k + 1];
        g_is64 = (odd == 0) ? 1 : 0;
    }

    for (int i = tid; i < 16 * 256; i += NTH) w2s[i] = w2[i];
    for (int i = tid; i < 256; i += NTH) w2s[16 * 256 + i] = b2[i];

    int op = tid & 7;            // o-pair: o = 2*op, 2*op+1
    int p = tid >> 3;            // node pair 0..19
    int nb = blockIdx.x * NPB;

    // load 2 nodes' x directly (broadcast across the 8 op lanes)
    unsigned long long xd[2][NODE_IN];
    #pragma unroll
    for (int j = 0; j < 2; j++) {
        const float4* xp = (const float4*)(x + (long long)(nb + 2 * p + j) * NODE_IN);
        #pragma unroll
        for (int q = 0; q < 4; q++) {
            float4 v = xp[q];
            xd[j][4 * q + 0] = pack_dup(v.x);
            xd[j][4 * q + 1] = pack_dup(v.y);
            xd[j][4 * q + 2] = pack_dup(v.z);
            xd[j][4 * q + 3] = pack_dup(v.w);
        }
    }
    __syncthreads();

    #pragma unroll 1
    for (int k = 0; k < 17; k++) {
        unsigned long long a0 = 0ull, a1 = 0ull;
        #pragma unroll
        for (int i = 0; i < NODE_IN; i++) {
            unsigned long long wp =
                *(const unsigned long long*)&w2s[k * 256 + i * 16 + 2 * op];  // LDS.64
            FFMA2(a0, xd[0][i], wp);
            FFMA2(a1, xd[1][i], wp);
        }
        float lo, hi;
        unpack2(a0, lo, hi);
        *(__half2*)&Tst[(2 * p) * SROW + k * 16 + 2 * op] = __floats2half2_rn(lo, hi);
        unpack2(a1, lo, hi);
        *(__half2*)&Tst[(2 * p + 1) * SROW + k * 16 + 2 * op] = __floats2half2_rn(lo, hi);
    }
    __syncthreads();
    tile_writeout(Tst, nb, tid);
}

// ---------------------------------------------------------------------------
// Edge pass, 8 lanes/edge, fp16 T, 5 x LDG.128 gather (640B/edge).
// Lane l in [0,8): uint4 load r holds halves k = 4r + (l>>1), o = (l&1)*8 + j.
// Bias row (k=16) lives in r=4 for l<2. Contraction in packed fp16 (HFMA2).
// Fold: split-exchange xor-4 then xor-2 reduce in fp32 -> 8 SHFL.
// Writers {0,1,4,5} each RED one o-quad. 256 threads = 32 edges/block.
__global__ void __launch_bounds__(256) k_edge(const float* __restrict__ ea,
                                              const void* __restrict__ eidx,
                                              const float* __restrict__ w1,
                                              const float* __restrict__ b1,
                                              int layer) {
    __shared__ float w1s[EDGE_IN * HID];
    __shared__ float b1s[HID];
    int tid = threadIdx.x;
    if (tid < EDGE_IN * HID) w1s[tid] = w1[tid];
    if (tid < HID) b1s[tid] = b1[tid];
    __syncthreads();

    int lane = tid & 31;
    int l = lane & 7;
    int a = l >> 1;
    int base = lane & ~7;                // 8-lane group base within warp
    int e = blockIdx.x * 32 + (tid >> 5) * 4 + (lane >> 3);

    int src, dst;
    if (g_is64) {
        const long long* ei = (const long long*)eidx;
        src = (int)ei[e];
        dst = (int)ei[N_EDGES + e];
    } else {
        const int* ei = (const int*)eidx;
        src = ei[e];
        dst = ei[N_EDGES + e];
    }

    // edge MLP: every lane loads all 8 ea values (broadcast within group)
    const float4* eap = (const float4*)(ea + (long long)e * EDGE_IN);
    float4 a0 = eap[0], a1 = eap[1];
    float eav[EDGE_IN] = {a0.x, a0.y, a0.z, a0.w, a1.x, a1.y, a1.z, a1.w};
    float hA = b1s[l], hB = b1s[l + 8];
    #pragma unroll
    for (int i = 0; i < EDGE_IN; i++) {
        hA += eav[i] * w1s[i * HID + l];
        hB += eav[i] * w1s[i * HID + l + 8];
    }
    hA = fmaxf(hA, 0.f);
    hB = fmaxf(hB, 0.f);

    // gather fp16 T: 5 x LDG.128, one 128B line per (r, edge)
    const uint4* tp = (const uint4*)(g_Th + (long long)src * TROWP_H);
    uint4 t[5];
    #pragma unroll
    for (int r = 0; r < 5; r++) t[r] = tp[r * 8 + l];

    // pack (hA,hB) -> half2; one shuffle moves both h values
    __half2 hpk = __floats2half2_rn(hA, hB);
    unsigned int hbits = *(unsigned int*)&hpk;
    unsigned int u0 = __shfl_sync(0xffffffffu, hbits, base + a);      // (h[a], h[8+a])
    unsigned int u1 = __shfl_sync(0xffffffffu, hbits, base + 4 + a);  // (h[4+a], h[12+a])
    __half2 h2_0 = *(__half2*)&u0;
    __half2 h2_1 = *(__half2*)&u1;
    __half2 hd[4];
    hd[0] = __low2half2(h2_0);   // h[a]
    hd[1] = __low2half2(h2_1);   // h[4+a]
    hd[2] = __high2half2(h2_0);  // h[8+a]
    hd[3] = __high2half2(h2_1);  // h[12+a]

    // fp16 packed contraction: 4-term HFMA2 chains per o-pair
    __half2 acc2[4];
    if (l < 2) {                         // bias row (k=16) in t[4]
        const __half2* bp = (const __half2*)&t[4];
        #pragma unroll
        for (int q = 0; q < 4; q++) acc2[q] = bp[q];
    } else {
        __half2 z = __floats2half2_rn(0.f, 0.f);
        #pragma unroll
        for (int q = 0; q < 4; q++) acc2[q] = z;
    }
    #pragma unroll
    for (int r = 0; r < 4; r++) {
        const __half2* hp = (const __half2*)&t[r];
        #pragma unroll
        for (int q = 0; q < 4; q++)
            acc2[q] = __hfma2(hd[r], hp[q], acc2[q]);
    }

    // convert 4 half2 accs -> 8 fp32
    float acc[8];
    #pragma unroll
    for (int q = 0; q < 4; q++) {
        float2 f = __half22float2(acc2[q]);
        acc[2 * q] = f.x;
        acc[2 * q + 1] = f.y;
    }

    // fold over a (4 lanes per parity): split-exchange then reduce -> 8 SHFL
    int s = (l >> 2) & 1;                // which quad this lane keeps
    float res[4];
    #pragma unroll
    for (int j = 0; j < 4; j++) {
        float send = s ? acc[j] : acc[j + 4];
        float got = __shfl_xor_sync(0xffffffffu, send, 4);
        res[j] = (s ? acc[j + 4] : acc[j]) + got;
    }
    #pragma unroll
    for (int j = 0; j < 4; j++)
        res[j] += __shfl_xor_sync(0xffffffffu, res[j], 2);

    if ((l & 2) == 0) {                  // writers: l in {0,1,4,5}
        int o0 = (l & 1) * 8 + (l >> 2) * 4;
        float* sum_out = (layer == 1) ? g_sum1 : g_sum2;
        float* p = sum_out + (long long)dst * HID + o0;
        asm volatile("red.global.add.v4.f32 [%0], {%1, %2, %3, %4};"
                     :: "l"(p), "f"(res[0]), "f"(res[1]),
                        "f"(res[2]), "f"(res[3])
                     : "memory");
    }
    if (layer == 1 && l == 0) atomicAdd(&g_cnt[dst], 1.f);
}

// ---------------------------------------------------------------------------
// Layer-1 update (scatter-mean + root + bias + relu) fused with layer-2
// precompute of T (fp16) from h1. Same staged-store structure.
__global__ void __launch_bounds__(NTH) k_update1_pre2(const float* __restrict__ x,
                                                      const float* __restrict__ root1,
                                                      const float* __restrict__ bias1,
                                                      const float* __restrict__ w2,
                                                      const float* __restrict__ b2) {
    __shared__ __align__(16) float w2s[17 * 256];   // rows 0-15: w2, row 16: b2
    __shared__ __align__(16) __half Tst[NPB * SROW];
    __shared__ __align__(16) float roots[NODE_IN * HID];
    __shared__ __align__(16) float biass[HID];
    __shared__ __align__(16) float hs[NPB * HID];
    int tid = threadIdx.x;
    for (int i = tid; i < 16 * 256; i += NTH) w2s[i] = w2[i];
    for (int i = tid; i < 256; i += NTH) w2s[16 * 256 + i] = b2[i];
    for (int i = tid; i < NODE_IN * HID; i += NTH) roots[i] = root1[i];
    if (tid < HID) biass[tid] = bias1[tid];

    int op = tid & 7;
    int p = tid >> 3;
    int nb = blockIdx.x * NPB;
    __syncthreads();

    // stage 1: layer-1 node update for 2 nodes x o-pair
    #pragma unroll
    for (int j = 0; j < 2; j++) {
        int n = nb + 2 * p + j;
        const float4* xp = (const float4*)(x + (long long)n * NODE_IN);
        unsigned long long xd[NODE_IN];
        #pragma unroll
        for (int q = 0; q < 4; q++) {
            float4 v = xp[q];
            xd[4 * q + 0] = pack_dup(v.x);
            xd[4 * q + 1] = pack_dup(v.y);
            xd[4 * q + 2] = pack_dup(v.z);
            xd[4 * q + 3] = pack_dup(v.w);
        }
        float inv = 1.f / fmaxf(g_cnt[n], 1.f);
        float2 sm = *(const float2*)&g_sum1[(long long)n * HID + 2 * op];
        unsigned long long acc =
            pack2(sm.x * inv + biass[2 * op], sm.y * inv + biass[2 * op + 1]);
        #pragma unroll
        for (int i = 0; i < NODE_IN; i++) {
            unsigned long long rp =
                *(const unsigned long long*)&roots[i * 16 + 2 * op];
            FFMA2(acc, xd[i & 15], rp);
        }
        float rx, ry;
        unpack2(acc, rx, ry);
        rx = fmaxf(rx, 0.f);
        ry = fmaxf(ry, 0.f);
        *(float2*)&g_h1[(long long)n * HID + 2 * op] = make_float2(rx, ry);
        *(float2*)&hs[(2 * p + j) * HID + 2 * op] = make_float2(rx, ry);
    }
    __syncthreads();

    // stage 2: layer-2 T precompute from h1
    unsigned long long hd[2][HID];
    #pragma unroll
    for (int j = 0; j < 2; j++)
        #pragma unroll
        for (int i = 0; i < HID; i++)
            hd[j][i] = pack_dup(hs[(2 * p + j) * HID + i]);

    #pragma unroll 1
    for (int k = 0; k < 17; k++) {
        unsigned long long a0 = 0ull, a1 = 0ull;
        #pragma unroll
        for (int i = 0; i < HID; i++) {
            unsigned long long wp =
                *(const unsigned long long*)&w2s[k * 256 + i * 16 + 2 * op];
            FFMA2(a0, hd[0][i], wp);
            FFMA2(a1, hd[1][i], wp);
        }
        float lo, hi;
        unpack2(a0, lo, hi);
        *(__half2*)&Tst[(2 * p) * SROW + k * 16 + 2 * op] = __floats2half2_rn(lo, hi);
        unpack2(a1, lo, hi);
        *(__half2*)&Tst[(2 * p + 1) * SROW + k * 16 + 2 * op] = __floats2half2_rn(lo, hi);
    }
    __syncthreads();
    tile_writeout(Tst, nb, tid);
}

// ---------------------------------------------------------------------------
// Layer-2 update + q head. One thread per node.
__global__ void __launch_bounds__(256) k_final(const float* __restrict__ root2,
                                               const float* __restrict__ bias2,
                                               const float* __restrict__ qw,
                                               const float* __restrict__ qb,
                                               float* __restrict__ out) {
    __shared__ float roots[HID * HID];
    __shared__ float biass[HID];
    __shared__ float qws[HID];
    int tid = threadIdx.x;
    roots[tid] = root2[tid];
    if (tid < HID) { biass[tid] = bias2[tid]; qws[tid] = qw[tid]; }
    __syncthreads();

    int n = blockIdx.x * 256 + tid;
    if (n >= N_NODES) return;
    float inv = 1.f / fmaxf(g_cnt[n], 1.f);
    float h1v[HID];
    const float4* h1p = (const float4*)&g_h1[(long long)n * HID];
    #pragma unroll
    for (int i = 0; i < HID / 4; i++) {
        float4 v = h1p[i];
        h1v[i * 4 + 0] = v.x; h1v[i * 4 + 1] = v.y;
        h1v[i * 4 + 2] = v.z; h1v[i * 4 + 3] = v.w;
    }
    float res = qb[0];
    #pragma unroll
    for (int o = 0; o < HID; o++) {
        float h2 = g_sum2[(long long)n * HID + o] * inv + biass[o];
        #pragma unroll
        for (int i = 0; i < HID; i++) h2 += h1v[i] * roots[i * HID + o];
        h2 = fmaxf(h2, 0.f);
        res += h2 * qws[o];
    }
    out[n] = res;
}

// ---------------------------------------------------------------------------
extern "C" void kernel_launch(void* const* d_in, const int* in_sizes, int n_in,
                              void* d_out, int out_size) {
    const float* x        = (const float*)d_in[0];
    const float* edge_attr= (const float*)d_in[1];
    const float* e1_w1    = (const float*)d_in[2];
    const float* e1_b1    = (const float*)d_in[3];
    const float* e1_w2    = (const float*)d_in[4];
    const float* e1_b2    = (const float*)d_in[5];
    const float* root1    = (const float*)d_in[6];
    const float* bias1    = (const float*)d_in[7];
    const float* e2_w1    = (const float*)d_in[8];
    const float* e2_b1    = (const float*)d_in[9];
    const float* e2_w2    = (const float*)d_in[10];
    const float* e2_b2    = (const float*)d_in[11];
    const float* root2    = (const float*)d_in[12];
    const float* bias2    = (const float*)d_in[13];
    const float* q_w      = (const float*)d_in[14];
    const float* q_b      = (const float*)d_in[15];
    const void*  eidx     = d_in[16];
    float* out = (float*)d_out;

    k_precompute<<<NODE_GRID, NTH>>>(x, e1_w2, e1_b2, (const int*)eidx);
    k_edge<<<N_EDGES / 32, 256>>>(edge_attr, eidx, e1_w1, e1_b1, 1);
    k_update1_pre2<<<NODE_GRID, NTH>>>(x, root1, bias1, e2_w2, e2_b2);
    k_edge<<<N_EDGES / 32, 256>>>(edge_attr, eidx, e2_w1, e2_b1, 2);
    k_final<<<(N_NODES + 255) / 256, 256>>>(root2, bias2, q_w, q_b, out);
}

// round 15
// speedup vs baseline: 1.7968x; 1.0003x over previous
#include <cuda_runtime.h>
#include <cuda_fp16.h>

#define N_NODES 50000
#define N_EDGES 400000
#define NODE_IN 16
#define EDGE_IN 8
#define HID 16
#define TROWP_H 320  // halves per node in gmem: 17x16 + pad -> 640B = 5 lines
#define NPB 40       // nodes per block in node kernels (50000 = 1250*40 exact)
#define NTH 160      // threads: 8 o-pairs x 20 node-pairs
#define NODE_GRID 1250
#define SROW 328     // halves per node row in smem tile (656B, bank-spread pad)

// PDL: successor may launch early; wait orders against predecessor completion.
#define PDL_TRIGGER() asm volatile("griddepcontrol.launch_dependents;" ::: "memory")
#define PDL_WAIT()    asm volatile("griddepcontrol.wait;" ::: "memory")

// Scratch (device globals: no allocation allowed)
__device__ __half g_Th[N_NODES * TROWP_H];  // factored tensor, fp16 (32 MB)
__device__ float g_sum1[N_NODES * HID];
__device__ float g_sum2[N_NODES * HID];
__device__ float g_cnt[N_NODES];
__device__ float g_h1[N_NODES * HID];

// f32x2 packed helpers (Blackwell packed fp32 pipe)
__device__ __forceinline__ unsigned long long pack_dup(float v) {
    unsigned long long r;
    asm("mov.b64 %0, {%1, %2};" : "=l"(r) : "f"(v), "f"(v));
    return r;
}
__device__ __forceinline__ unsigned long long pack2(float x, float y) {
    unsigned long long r;
    asm("mov.b64 %0, {%1, %2};" : "=l"(r) : "f"(x), "f"(y));
    return r;
}
__device__ __forceinline__ void unpack2(unsigned long long v, float& x, float& y) {
    asm("mov.b64 {%0, %1}, %2;" : "=f"(x), "=f"(y) : "l"(v));
}
#define FFMA2(acc, a, b) \
    asm("fma.rn.f32x2 %0, %1, %2, %0;" : "+l"(acc) : "l"(a), "l"(b))

// Coalesced writeout of the staged T tile: NPB*640B as uint4, 10 per thread.
__device__ __forceinline__ void tile_writeout(const __half* Tst, int nb, int tid) {
    const char* sbase = (const char*)Tst;
    char* gbase = (char*)(g_Th + (long long)nb * TROWP_H);
    #pragma unroll
    for (int j = 0; j < 10; j++) {
        int idx = tid + j * NTH;         // 0..1599 uint4 slots
        int node = idx / 40;
        int w16 = idx % 40;              // 16B chunk within node row
        uint4 v = *(const uint4*)(sbase + node * 656 + w16 * 16);
        *(uint4*)(gbase + node * 640 + w16 * 16) = v;
    }
}

// ---------------------------------------------------------------------------
// Layer-1 per-node precompute: T[n][k][o] = sum_i x[n,i] * w2[k, i*16+o]
//                              row 16     = sum_i x[n,i] * b2[i*16+o]
// Thread = (o-pair, 2 nodes); LDS.64 weight pairs; fma.rn.f32x2 inner op.
// T staged in smem (conflict-free STS), written out coalesced as uint4.
// Fused: accumulator zeroing.
__global__ void __launch_bounds__(NTH) k_precompute(const float* __restrict__ x,
                                                    const float* __restrict__ w2,
                                                    const float* __restrict__ b2) {
    __shared__ __align__(16) float w2s[17 * 256];   // rows 0-15: w2, row 16: b2
    __shared__ __align__(16) __half Tst[NPB * SROW];
    int tid = threadIdx.x;
    int gid = blockIdx.x * NTH + tid;
    PDL_TRIGGER();

    // fused zeroing of accumulators (kernel boundary orders vs. edge pass)
    const int TOT = NODE_GRID * NTH;    // 200000
    for (int j = gid; j < N_NODES * HID; j += TOT) { g_sum1[j] = 0.f; g_sum2[j] = 0.f; }
    if (gid < N_NODES) g_cnt[gid] = 0.f;

    for (int i = tid; i < 16 * 256; i += NTH) w2s[i] = w2[i];
    for (int i = tid; i < 256; i += NTH) w2s[16 * 256 + i] = b2[i];

    int op = tid & 7;            // o-pair: o = 2*op, 2*op+1
    int p = tid >> 3;            // node pair 0..19
    int nb = blockIdx.x * NPB;

    // load 2 nodes' x directly (broadcast across the 8 op lanes)
    unsigned long long xd[2][NODE_IN];
    #pragma unroll
    for (int j = 0; j < 2; j++) {
        const float4* xp = (const float4*)(x + (long long)(nb + 2 * p + j) * NODE_IN);
        #pragma unroll
        for (int q = 0; q < 4; q++) {
            float4 v = xp[q];
            xd[j][4 * q + 0] = pack_dup(v.x);
            xd[j][4 * q + 1] = pack_dup(v.y);
            xd[j][4 * q + 2] = pack_dup(v.z);
            xd[j][4 * q + 3] = pack_dup(v.w);
        }
    }
    __syncthreads();

    #pragma unroll 1
    for (int k = 0; k < 17; k++) {
        unsigned long long a0 = 0ull, a1 = 0ull;
        #pragma unroll
        for (int i = 0; i < NODE_IN; i++) {
            unsigned long long wp =
                *(const unsigned long long*)&w2s[k * 256 + i * 16 + 2 * op];  // LDS.64
            FFMA2(a0, xd[0][i], wp);
            FFMA2(a1, xd[1][i], wp);
        }
        float lo, hi;
        unpack2(a0, lo, hi);
        *(__half2*)&Tst[(2 * p) * SROW + k * 16 + 2 * op] = __floats2half2_rn(lo, hi);
        unpack2(a1, lo, hi);
        *(__half2*)&Tst[(2 * p + 1) * SROW + k * 16 + 2 * op] = __floats2half2_rn(lo, hi);
    }
    __syncthreads();
    tile_writeout(Tst, nb, tid);
}

// ---------------------------------------------------------------------------
// Edge pass, 8 lanes/edge, fp16 T, 5 x LDG.128 gather (640B/edge).
// Lane l in [0,8): uint4 load r holds halves k = 4r + (l>>1), o = (l&1)*8 + j.
// Bias row (k=16) lives in r=4 for l<2. Contraction in packed fp16 (HFMA2).
// Fold: split-exchange xor-4 then xor-2 reduce in fp32 -> 8 SHFL.
// Writers {0,1,4,5} each RED one o-quad. 256 threads = 32 edges/block.
// PDL: prologue (w1 smem, idx/ea loads, edge MLP) runs pre-wait; T gather
// and REDs run post-wait. Index width detected per-CTA from raw input.
__global__ void __launch_bounds__(256) k_edge(const float* __restrict__ ea,
                                              const void* __restrict__ eidx,
                                              const float* __restrict__ w1,
                                              const float* __restrict__ b1,
                                              int layer) {
    __shared__ float w1s[EDGE_IN * HID];
    __shared__ float b1s[HID];
    __shared__ int s_is64;
    int tid = threadIdx.x;
    PDL_TRIGGER();
    if (tid < EDGE_IN * HID) w1s[tid] = w1[tid];
    if (tid < HID) b1s[tid] = b1[tid];
    if (tid == 0) {
        // int64 vs int32 detection from the input itself (values < 50000 ->
        // int64 high words all zero; 8 consecutive zero odd-words ~ impossible
        // for int32 payload)
        const int* ei_raw = (const int*)eidx;
        int odd = 0;
        #pragma unroll
        for (int k = 0; k < 8; k++) odd |= ei_raw[2 * k + 1];
        s_is64 = (odd == 0) ? 1 : 0;
    }
    __syncthreads();

    int lane = tid & 31;
    int l = lane & 7;
    int a = l >> 1;
    int base = lane & ~7;                // 8-lane group base within warp
    int e = blockIdx.x * 32 + (tid >> 5) * 4 + (lane >> 3);

    int src, dst;
    if (s_is64) {
        const long long* ei = (const long long*)eidx;
        src = (int)ei[e];
        dst = (int)ei[N_EDGES + e];
    } else {
        const int* ei = (const int*)eidx;
        src = ei[e];
        dst = ei[N_EDGES + e];
    }

    // edge MLP: every lane loads all 8 ea values (broadcast within group)
    const float4* eap = (const float4*)(ea + (long long)e * EDGE_IN);
    float4 a0 = eap[0], a1 = eap[1];
    float eav[EDGE_IN] = {a0.x, a0.y, a0.z, a0.w, a1.x, a1.y, a1.z, a1.w};
    float hA = b1s[l], hB = b1s[l + 8];
    #pragma unroll
    for (int i = 0; i < EDGE_IN; i++) {
        hA += eav[i] * w1s[i * HID + l];
        hB += eav[i] * w1s[i * HID + l + 8];
    }
    hA = fmaxf(hA, 0.f);
    hB = fmaxf(hB, 0.f);

    // pack (hA,hB) -> half2; one shuffle moves both h values
    __half2 hpk = __floats2half2_rn(hA, hB);
    unsigned int hbits = *(unsigned int*)&hpk;
    unsigned int u0 = __shfl_sync(0xffffffffu, hbits, base + a);      // (h[a], h[8+a])
    unsigned int u1 = __shfl_sync(0xffffffffu, hbits, base + 4 + a);  // (h[4+a], h[12+a])
    __half2 h2_0 = *(__half2*)&u0;
    __half2 h2_1 = *(__half2*)&u1;
    __half2 hd[4];
    hd[0] = __low2half2(h2_0);   // h[a]
    hd[1] = __low2half2(h2_1);   // h[4+a]
    hd[2] = __high2half2(h2_0);  // h[8+a]
    hd[3] = __high2half2(h2_1);  // h[12+a]

    // ---- wait for predecessor (T producer / accumulator zeroing) ----
    PDL_WAIT();

    // gather fp16 T: 5 x LDG.128, one 128B line per (r, edge)
    const uint4* tp = (const uint4*)(g_Th + (long long)src * TROWP_H);
    uint4 t[5];
    #pragma unroll
    for (int r = 0; r < 5; r++) t[r] = tp[r * 8 + l];

    // fp16 packed contraction: 4-term HFMA2 chains per o-pair
    __half2 acc2[4];
    if (l < 2) {                         // bias row (k=16) in t[4]
        const __half2* bp = (const __half2*)&t[4];
        #pragma unroll
        for (int q = 0; q < 4; q++) acc2[q] = bp[q];
    } else {
        __half2 z = __floats2half2_rn(0.f, 0.f);
        #pragma unroll
        for (int q = 0; q < 4; q++) acc2[q] = z;
    }
    #pragma unroll
    for (int r = 0; r < 4; r++) {
        const __half2* hp = (const __half2*)&t[r];
        #pragma unroll
        for (int q = 0; q < 4; q++)
            acc2[q] = __hfma2(hd[r], hp[q], acc2[q]);
    }

    // convert 4 half2 accs -> 8 fp32
    float acc[8];
    #pragma unroll
    for (int q = 0; q < 4; q++) {
        float2 f = __half22float2(acc2[q]);
        acc[2 * q] = f.x;
        acc[2 * q + 1] = f.y;
    }

    // fold over a (4 lanes per parity): split-exchange then reduce -> 8 SHFL
    int s = (l >> 2) & 1;                // which quad this lane keeps
    float res[4];
    #pragma unroll
    for (int j = 0; j < 4; j++) {
        float send = s ? acc[j] : acc[j + 4];
        float got = __shfl_xor_sync(0xffffffffu, send, 4);
        res[j] = (s ? acc[j + 4] : acc[j]) + got;
    }
    #pragma unroll
    for (int j = 0; j < 4; j++)
        res[j] += __shfl_xor_sync(0xffffffffu, res[j], 2);

    if ((l & 2) == 0) {                  // writers: l in {0,1,4,5}
        int o0 = (l & 1) * 8 + (l >> 2) * 4;
        float* sum_out = (layer == 1) ? g_sum1 : g_sum2;
        float* p = sum_out + (long long)dst * HID + o0;
        asm volatile("red.global.add.v4.f32 [%0], {%1, %2, %3, %4};"
                     :: "l"(p), "f"(res[0]), "f"(res[1]),
                        "f"(res[2]), "f"(res[3])
                     : "memory");
    }
    if (layer == 1 && l == 0) atomicAdd(&g_cnt[dst], 1.f);
}

// ---------------------------------------------------------------------------
// Layer-1 update (scatter-mean + root + bias + relu) fused with layer-2
// precompute of T (fp16) from h1. PDL: weight smem loads + x prefetch
// pre-wait; g_cnt/g_sum1 reads post-wait.
__global__ void __launch_bounds__(NTH) k_update1_pre2(const float* __restrict__ x,
                                                      const float* __restrict__ root1,
                                                      const float* __restrict__ bias1,
                                                      const float* __restrict__ w2,
                                                      const float* __restrict__ b2) {
    __shared__ __align__(16) float w2s[17 * 256];   // rows 0-15: w2, row 16: b2
    __shared__ __align__(16) __half Tst[NPB * SROW];
    __shared__ __align__(16) float roots[NODE_IN * HID];
    __shared__ __align__(16) float biass[HID];
    __shared__ __align__(16) float hs[NPB * HID];
    int tid = threadIdx.x;
    PDL_TRIGGER();
    for (int i = tid; i < 16 * 256; i += NTH) w2s[i] = w2[i];
    for (int i = tid; i < 256; i += NTH) w2s[16 * 256 + i] = b2[i];
    for (int i = tid; i < NODE_IN * HID; i += NTH) roots[i] = root1[i];
    if (tid < HID) biass[tid] = bias1[tid];

    int op = tid & 7;
    int p = tid >> 3;
    int nb = blockIdx.x * NPB;

    // prefetch x for this thread's 2 nodes (input; pre-wait)
    float4 xr[2][4];
    #pragma unroll
    for (int j = 0; j < 2; j++) {
        const float4* xp = (const float4*)(x + (long long)(nb + 2 * p + j) * NODE_IN);
        #pragma unroll
        for (int q = 0; q < 4; q++) xr[j][q] = xp[q];
    }
    __syncthreads();

    // ---- wait for edge pass 1 (g_sum1 / g_cnt producers) ----
    PDL_WAIT();

    // stage 1: layer-1 node update for 2 nodes x o-pair
    #pragma unroll
    for (int j = 0; j < 2; j++) {
        int n = nb + 2 * p + j;
        unsigned long long xd[NODE_IN];
        #pragma unroll
        for (int q = 0; q < 4; q++) {
            float4 v = xr[j][q];
            xd[4 * q + 0] = pack_dup(v.x);
            xd[4 * q + 1] = pack_dup(v.y);
            xd[4 * q + 2] = pack_dup(v.z);
            xd[4 * q + 3] = pack_dup(v.w);
        }
        float inv = 1.f / fmaxf(g_cnt[n], 1.f);
        float2 sm = *(const float2*)&g_sum1[(long long)n * HID + 2 * op];
        unsigned long long acc =
            pack2(sm.x * inv + biass[2 * op], sm.y * inv + biass[2 * op + 1]);
        #pragma unroll
        for (int i = 0; i < NODE_IN; i++) {
            unsigned long long rp =
                *(const unsigned long long*)&roots[i * 16 + 2 * op];
            FFMA2(acc, xd[i & 15], rp);
        }
        float rx, ry;
        unpack2(acc, rx, ry);
        rx = fmaxf(rx, 0.f);
        ry = fmaxf(ry, 0.f);
        *(float2*)&g_h1[(long long)n * HID + 2 * op] = make_float2(rx, ry);
        *(float2*)&hs[(2 * p + j) * HID + 2 * op] = make_float2(rx, ry);
    }
    __syncthreads();

    // stage 2: layer-2 T precompute from h1
    unsigned long long hd[2][HID];
    #pragma unroll
    for (int j = 0; j < 2; j++)
        #pragma unroll
        for (int i = 0; i < HID; i++)
            hd[j][i] = pack_dup(hs[(2 * p + j) * HID + i]);

    #pragma unroll 1
    for (int k = 0; k < 17; k++) {
        unsigned long long a0 = 0ull, a1 = 0ull;
        #pragma unroll
        for (int i = 0; i < HID; i++) {
            unsigned long long wp =
                *(const unsigned long long*)&w2s[k * 256 + i * 16 + 2 * op];
            FFMA2(a0, hd[0][i], wp);
            FFMA2(a1, hd[1][i], wp);
        }
        float lo, hi;
        unpack2(a0, lo, hi);
        *(__half2*)&Tst[(2 * p) * SROW + k * 16 + 2 * op] = __floats2half2_rn(lo, hi);
        unpack2(a1, lo, hi);
        *(__half2*)&Tst[(2 * p + 1) * SROW + k * 16 + 2 * op] = __floats2half2_rn(lo, hi);
    }
    __syncthreads();
    tile_writeout(Tst, nb, tid);
}

// ---------------------------------------------------------------------------
// Layer-2 update + q head. One thread per node. PDL: weight smem pre-wait.
__global__ void __launch_bounds__(256) k_final(const float* __restrict__ root2,
                                               const float* __restrict__ bias2,
                                               const float* __restrict__ qw,
                                               const float* __restrict__ qb,
                                               float* __restrict__ out) {
    __shared__ float roots[HID * HID];
    __shared__ float biass[HID];
    __shared__ float qws[HID];
    int tid = threadIdx.x;
    PDL_TRIGGER();
    roots[tid] = root2[tid];
    if (tid < HID) { biass[tid] = bias2[tid]; qws[tid] = qw[tid]; }
    __syncthreads();

    // ---- wait for edge pass 2 (g_sum2 producer) ----
    PDL_WAIT();

    int n = blockIdx.x * 256 + tid;
    if (n >= N_NODES) return;
    float inv = 1.f / fmaxf(g_cnt[n], 1.f);
    float h1v[HID];
    const float4* h1p = (const float4*)&g_h1[(long long)n * HID];
    #pragma unroll
    for (int i = 0; i < HID / 4; i++) {
        float4 v = h1p[i];
        h1v[i * 4 + 0] = v.x; h1v[i * 4 + 1] = v.y;
        h1v[i * 4 + 2] = v.z; h1v[i * 4 + 3] = v.w;
    }
    float res = qb[0];
    #pragma unroll
    for (int o = 0; o < HID; o++) {
        float h2 = g_sum2[(long long)n * HID + o] * inv + biass[o];
        #pragma unroll
        for (int i = 0; i < HID; i++) h2 += h1v[i] * roots[i * HID + o];
        h2 = fmaxf(h2, 0.f);
        res += h2 * qws[o];
    }
    out[n] = res;
}

// ---------------------------------------------------------------------------
extern "C" void kernel_launch(void* const* d_in, const int* in_sizes, int n_in,
                              void* d_out, int out_size) {
    const float* x        = (const float*)d_in[0];
    const float* edge_attr= (const float*)d_in[1];
    const float* e1_w1    = (const float*)d_in[2];
    const float* e1_b1    = (const float*)d_in[3];
    const float* e1_w2    = (const float*)d_in[4];
    const float* e1_b2    = (const float*)d_in[5];
    const float* root1    = (const float*)d_in[6];
    const float* bias1    = (const float*)d_in[7];
    const float* e2_w1    = (const float*)d_in[8];
    const float* e2_b1    = (const float*)d_in[9];
    const float* e2_w2    = (const float*)d_in[10];
    const float* e2_b2    = (const float*)d_in[11];
    const float* root2    = (const float*)d_in[12];
    const float* bias2    = (const float*)d_in[13];
    const float* q_w      = (const float*)d_in[14];
    const float* q_b      = (const float*)d_in[15];
    const void*  eidx     = d_in[16];
    float* out = (float*)d_out;

    // PDL launch attribute for kernels 2-5 (programmatic stream serialization)
    cudaLaunchAttribute pdl_attr[1];
    pdl_attr[0].id = cudaLaunchAttributeProgrammaticStreamSerialization;
    pdl_attr[0].val.programmaticStreamSerializationAllowed = 1;

    // kernel 1: normal launch
    k_precompute<<<NODE_GRID, NTH>>>(x, e1_w2, e1_b2);

    {   // kernel 2: edge pass layer 1
        cudaLaunchConfig_t cfg = {};
        cfg.gridDim = dim3(N_EDGES / 32);
        cfg.blockDim = dim3(256);
        cfg.attrs = pdl_attr;
        cfg.numAttrs = 1;
        cudaLaunchKernelEx(&cfg, k_edge, edge_attr, (const void*)eidx,
                           e1_w1, e1_b1, 1);
    }
    {   // kernel 3: update1 + precompute2
        cudaLaunchConfig_t cfg = {};
        cfg.gridDim = dim3(NODE_GRID);
        cfg.blockDim = dim3(NTH);
        cfg.attrs = pdl_attr;
        cfg.numAttrs = 1;
        cudaLaunchKernelEx(&cfg, k_update1_pre2, x, root1, bias1, e2_w2, e2_b2);
    }
    {   // kernel 4: edge pass layer 2
        cudaLaunchConfig_t cfg = {};
        cfg.gridDim = dim3(N_EDGES / 32);
        cfg.blockDim = dim3(256);
        cfg.attrs = pdl_attr;
        cfg.numAttrs = 1;
        cudaLaunchKernelEx(&cfg, k_edge, edge_attr, (const void*)eidx,
                           e2_w1, e2_b1, 2);
    }
    {   // kernel 5: final update + q head
        cudaLaunchConfig_t cfg = {};
        cfg.gridDim = dim3((N_NODES + 255) / 256);
        cfg.blockDim = dim3(256);
        cfg.attrs = pdl_attr;
        cfg.numAttrs = 1;
        cudaLaunchKernelEx(&cfg, k_final, root2, bias2, q_w, q_b, out);
    }
}